// round 3
// baseline (speedup 1.0000x reference)
#include <cuda_runtime.h>
#include <cuda_bf16.h>
#include <math.h>
#include <stdint.h>

// Problem constants
#define LQ   512
#define LK   4096
#define BB   4
#define DD   512
#define DFF  2048
#define HH   8
#define HD   64
#define LN_EPS 1e-5f

// ------------------------- scratch (device globals) -----------------------
__device__ float g_t  [LQ * BB * DD];
__device__ float g_m  [LK * BB * DD];
__device__ float g_q  [LQ * BB * DD];
__device__ float g_k  [LK * BB * DD];
__device__ float g_v  [LK * BB * DD];
__device__ float g_ctx[LQ * BB * DD];
__device__ float g_x1 [LQ * BB * DD];
__device__ float g_xn [LQ * BB * DD];
__device__ float g_ff1[LQ * BB * DFF];

// ------------------------- reductions ------------------------------------
__device__ __forceinline__ float warpReduceSum(float v) {
    #pragma unroll
    for (int o = 16; o > 0; o >>= 1) v += __shfl_down_sync(0xffffffffu, v, o);
    return v;
}
__device__ __forceinline__ float warpReduceMax(float v) {
    #pragma unroll
    for (int o = 16; o > 0; o >>= 1) v = fmaxf(v, __shfl_down_sync(0xffffffffu, v, o));
    return v;
}
__device__ __forceinline__ float blockReduceSum256(float v, float* shared) {
    __syncthreads();
    int lane = threadIdx.x & 31, wid = threadIdx.x >> 5;
    v = warpReduceSum(v);
    if (lane == 0) shared[wid] = v;
    __syncthreads();
    if (wid == 0) {
        float x = (lane < 8) ? shared[lane] : 0.f;
        #pragma unroll
        for (int o = 4; o > 0; o >>= 1) x += __shfl_down_sync(0xffffffffu, x, o);
        if (lane == 0) shared[0] = x;
    }
    __syncthreads();
    return shared[0];
}

// ------------------------- LayerNorm (row length 512) ---------------------
__global__ void ln_kernel(const float* __restrict__ in,
                          const float* __restrict__ w,
                          const float* __restrict__ b,
                          float* __restrict__ out)
{
    __shared__ float red[8];
    const int r = blockIdx.x;
    const float* xp = in + (size_t)r * DD;
    float* op = out + (size_t)r * DD;
    int t = threadIdx.x;

    float x0 = xp[t], x1 = xp[t + 256];
    float s = blockReduceSum256(x0 + x1, red);
    float mu = s * (1.0f / DD);
    float d0 = x0 - mu, d1 = x1 - mu;
    float ss = blockReduceSum256(d0 * d0 + d1 * d1, red);
    float rstd = rsqrtf(ss * (1.0f / DD) + LN_EPS);
    op[t]       = d0 * rstd * w[t]       + b[t];
    op[t + 256] = d1 * rstd * w[t + 256] + b[t + 256];
}

// ------------------------- tf32 helpers ------------------------------------
__device__ __forceinline__ float to_tf32(float x) {
    uint32_t r;
    asm("cvt.rna.tf32.f32 %0, %1;" : "=r"(r) : "f"(x));
    return __uint_as_float(r);
}
__device__ __forceinline__ void mma_tf32(float* d, const float* a, const float* b) {
    asm volatile(
        "mma.sync.aligned.m16n8k8.row.col.f32.tf32.tf32.f32 "
        "{%0,%1,%2,%3}, {%4,%5,%6,%7}, {%8,%9}, {%0,%1,%2,%3};"
        : "+f"(d[0]), "+f"(d[1]), "+f"(d[2]), "+f"(d[3])
        : "r"(__float_as_uint(a[0])), "r"(__float_as_uint(a[1])),
          "r"(__float_as_uint(a[2])), "r"(__float_as_uint(a[3])),
          "r"(__float_as_uint(b[0])), "r"(__float_as_uint(b[1])));
}

// ------------------------- GEMM: out[R,N] = A[R,K] @ W[N,K]^T + bias ------
// 128x128x16 tiles, 256 threads = 8 warps (2Mx4N), warp tile 64x32.
// 3xTF32 split for fp32-class accuracy. [m][k] smem, KS=20 stride.
#define GBM 128
#define GBN 128
#define GBK 16
#define KS  20
#define SMEM_GEMM (2 * 4 * GBM * KS * 4)   // 2 bufs x (Ah,Al,Bh,Bl) x 128x20 floats

__global__ __launch_bounds__(256) void gemm_tf32(
        const float* __restrict__ A,
        const float* __restrict__ W,
        const float* __restrict__ bias,
        const float* __restrict__ res,
        float* __restrict__ out,
        int R, int N, int K, int doRelu)
{
    extern __shared__ float smem[];
    float* sAh = smem;                       // [2][GBM*KS]
    float* sAl = sAh + 2 * GBM * KS;
    float* sBh = sAl + 2 * GBM * KS;
    float* sBl = sBh + 2 * GBN * KS;

    const int tid  = threadIdx.x;
    const int lane = tid & 31;
    const int warp = tid >> 5;
    const int g = lane >> 2, t = lane & 3;
    const int mW = (warp & 1) * 64;
    const int nW = (warp >> 1) * 32;
    const int rowBase = blockIdx.y * GBM;
    const int colBase = blockIdx.x * GBN;

    // global load mapping: 2 float4 per thread per operand tile
    const int lr = tid >> 2;          // 0..63
    const int lc = (tid & 3) * 4;     // 0,4,8,12
    const float* Ag0 = A + (size_t)(rowBase + lr) * K + lc;
    const float* Ag1 = A + (size_t)(rowBase + lr + 64) * K + lc;
    const float* Wg0 = W + (size_t)(colBase + lr) * K + lc;
    const float* Wg1 = W + (size_t)(colBase + lr + 64) * K + lc;

    float acc[4][4][4];
    #pragma unroll
    for (int i = 0; i < 4; i++)
        #pragma unroll
        for (int j = 0; j < 4; j++)
            #pragma unroll
            for (int c = 0; c < 4; c++) acc[i][j][c] = 0.f;

    float4 ra0, ra1, rw0, rw1;

    // stage helper expressed inline twice via macro
#define STAGE(BUF)                                                             \
    {                                                                          \
        int ofs = (BUF) * GBM * KS;                                            \
        float4 v, h4, l4;                                                      \
        v = ra0;                                                               \
        h4.x = to_tf32(v.x); l4.x = to_tf32(v.x - h4.x);                       \
        h4.y = to_tf32(v.y); l4.y = to_tf32(v.y - h4.y);                       \
        h4.z = to_tf32(v.z); l4.z = to_tf32(v.z - h4.z);                       \
        h4.w = to_tf32(v.w); l4.w = to_tf32(v.w - h4.w);                       \
        *(float4*)(sAh + ofs + lr * KS + lc) = h4;                             \
        *(float4*)(sAl + ofs + lr * KS + lc) = l4;                             \
        v = ra1;                                                               \
        h4.x = to_tf32(v.x); l4.x = to_tf32(v.x - h4.x);                       \
        h4.y = to_tf32(v.y); l4.y = to_tf32(v.y - h4.y);                       \
        h4.z = to_tf32(v.z); l4.z = to_tf32(v.z - h4.z);                       \
        h4.w = to_tf32(v.w); l4.w = to_tf32(v.w - h4.w);                       \
        *(float4*)(sAh + ofs + (lr + 64) * KS + lc) = h4;                      \
        *(float4*)(sAl + ofs + (lr + 64) * KS + lc) = l4;                      \
        v = rw0;                                                               \
        h4.x = to_tf32(v.x); l4.x = to_tf32(v.x - h4.x);                       \
        h4.y = to_tf32(v.y); l4.y = to_tf32(v.y - h4.y);                       \
        h4.z = to_tf32(v.z); l4.z = to_tf32(v.z - h4.z);                       \
        h4.w = to_tf32(v.w); l4.w = to_tf32(v.w - h4.w);                       \
        *(float4*)(sBh + ofs + lr * KS + lc) = h4;                             \
        *(float4*)(sBl + ofs + lr * KS + lc) = l4;                             \
        v = rw1;                                                               \
        h4.x = to_tf32(v.x); l4.x = to_tf32(v.x - h4.x);                       \
        h4.y = to_tf32(v.y); l4.y = to_tf32(v.y - h4.y);                       \
        h4.z = to_tf32(v.z); l4.z = to_tf32(v.z - h4.z);                       \
        h4.w = to_tf32(v.w); l4.w = to_tf32(v.w - h4.w);                       \
        *(float4*)(sBh + ofs + (lr + 64) * KS + lc) = h4;                      \
        *(float4*)(sBl + ofs + (lr + 64) * KS + lc) = l4;                      \
    }

#define COMPUTE(BUF)                                                           \
    {                                                                          \
        const int ofs = (BUF) * GBM * KS;                                      \
        _Pragma("unroll")                                                      \
        for (int kb = 0; kb < GBK; kb += 8) {                                  \
            float ah[4][4], al[4][4], bh[4][2], bl[4][2];                      \
            _Pragma("unroll")                                                  \
            for (int mf = 0; mf < 4; mf++) {                                   \
                int r0 = mW + mf * 16 + g;                                     \
                ah[mf][0] = sAh[ofs + r0 * KS + kb + t];                       \
                ah[mf][1] = sAh[ofs + (r0 + 8) * KS + kb + t];                 \
                ah[mf][2] = sAh[ofs + r0 * KS + kb + t + 4];                   \
                ah[mf][3] = sAh[ofs + (r0 + 8) * KS + kb + t + 4];             \
                al[mf][0] = sAl[ofs + r0 * KS + kb + t];                       \
                al[mf][1] = sAl[ofs + (r0 + 8) * KS + kb + t];                 \
                al[mf][2] = sAl[ofs + r0 * KS + kb + t + 4];                   \
                al[mf][3] = sAl[ofs + (r0 + 8) * KS + kb + t + 4];             \
            }                                                                  \
            _Pragma("unroll")                                                  \
            for (int nf = 0; nf < 4; nf++) {                                   \
                int c0 = nW + nf * 8 + g;                                      \
                bh[nf][0] = sBh[ofs + c0 * KS + kb + t];                       \
                bh[nf][1] = sBh[ofs + c0 * KS + kb + t + 4];                   \
                bl[nf][0] = sBl[ofs + c0 * KS + kb + t];                       \
                bl[nf][1] = sBl[ofs + c0 * KS + kb + t + 4];                   \
            }                                                                  \
            _Pragma("unroll")                                                  \
            for (int mf = 0; mf < 4; mf++)                                     \
                _Pragma("unroll")                                              \
                for (int nf = 0; nf < 4; nf++) {                               \
                    mma_tf32(acc[mf][nf], ah[mf], bh[nf]);                     \
                    mma_tf32(acc[mf][nf], ah[mf], bl[nf]);                     \
                    mma_tf32(acc[mf][nf], al[mf], bh[nf]);                     \
                }                                                              \
        }                                                                      \
    }

    // prologue
    ra0 = *(const float4*)(Ag0);
    ra1 = *(const float4*)(Ag1);
    rw0 = *(const float4*)(Wg0);
    rw1 = *(const float4*)(Wg1);
    STAGE(0);
    __syncthreads();

    const int nT = K / GBK;
    int buf = 0;
    for (int tt = 1; tt < nT; tt++) {
        ra0 = *(const float4*)(Ag0 + tt * GBK);
        ra1 = *(const float4*)(Ag1 + tt * GBK);
        rw0 = *(const float4*)(Wg0 + tt * GBK);
        rw1 = *(const float4*)(Wg1 + tt * GBK);
        COMPUTE(buf);
        STAGE(buf ^ 1);
        __syncthreads();
        buf ^= 1;
    }
    COMPUTE(buf);

    // epilogue: c0,c1 -> (row, 2t/2t+1); c2,c3 -> (row+8, ...)
    #pragma unroll
    for (int mf = 0; mf < 4; mf++) {
        int row0 = rowBase + mW + mf * 16 + g;
        #pragma unroll
        for (int nf = 0; nf < 4; nf++) {
            int col = colBase + nW + nf * 8 + 2 * t;
            float2 bb = *(const float2*)(bias + col);
            float2 v0, v1;
            v0.x = acc[mf][nf][0] + bb.x; v0.y = acc[mf][nf][1] + bb.y;
            v1.x = acc[mf][nf][2] + bb.x; v1.y = acc[mf][nf][3] + bb.y;
            if (doRelu) {
                v0.x = fmaxf(v0.x, 0.f); v0.y = fmaxf(v0.y, 0.f);
                v1.x = fmaxf(v1.x, 0.f); v1.y = fmaxf(v1.y, 0.f);
            }
            if (res) {
                float2 r0 = *(const float2*)(res + (size_t)row0 * N + col);
                float2 r1 = *(const float2*)(res + (size_t)(row0 + 8) * N + col);
                v0.x += r0.x; v0.y += r0.y;
                v1.x += r1.x; v1.y += r1.y;
            }
            *(float2*)(out + (size_t)row0 * N + col) = v0;
            *(float2*)(out + (size_t)(row0 + 8) * N + col) = v1;
        }
    }
}

// ------------------------- fused banded attention -------------------------
// QT query rows per block, all 8 heads. 512 threads, dynamic smem.
#define QT 4
#define SW 832
#define SMEM_ATTN ((QT*DD + QT*HH*SW + QT*HH) * 4)
#define ATHR 512

__global__ __launch_bounds__(ATHR) void attn_kernel(
        const float* __restrict__ q,
        const float* __restrict__ k,
        const float* __restrict__ v,
        float* __restrict__ ctx,
        float* __restrict__ aw)
{
    extern __shared__ float smem[];
    float* sQ   = smem;                    // QT*DD
    float* sS   = smem + QT * DD;          // QT*HH*SW
    float* sInv = sS + QT * HH * SW;       // QT*HH

    const int qi0 = blockIdx.x * QT;
    const int b   = blockIdx.y;
    const int tid = threadIdx.x;

    int start[QT], wd[QT];
    #pragma unroll
    for (int r = 0; r < QT; r++) {
        int qi = qi0 + r;
        if (qi >= 409) { start[r] = 3268; wd[r] = 828; }
        else           { start[r] = qi * 8; wd[r] = 827; }
    }
    const int ustart = start[0];
    const int uend   = start[QT-1] + wd[QT-1];
    const int uW     = uend - ustart;

    for (int i = tid; i < QT * DD; i += ATHR) {
        int r = i / DD, c = i % DD;
        sQ[i] = q[((size_t)(qi0 + r) * BB + b) * DD + c];
    }
    __syncthreads();

    const float scale = 0.125f;  // 1/sqrt(64)

    // scores over the union band
    for (int idx = tid; idx < uW; idx += ATHR) {
        const int gk = ustart + idx;
        const float4* kp = (const float4*)(k + ((size_t)gk * BB + b) * DD);
        int jj[QT]; bool in[QT];
        #pragma unroll
        for (int r = 0; r < QT; r++) {
            jj[r] = gk - start[r];
            in[r] = (jj[r] >= 0) && (jj[r] < wd[r]);
        }
        #pragma unroll
        for (int h = 0; h < HH; h++) {
            float acc[QT];
            #pragma unroll
            for (int r = 0; r < QT; r++) acc[r] = 0.f;
            #pragma unroll
            for (int c = 0; c < 16; c++) {
                float4 kv = kp[h * 16 + c];
                #pragma unroll
                for (int r = 0; r < QT; r++) {
                    float4 qv = ((const float4*)(sQ + r * DD))[h * 16 + c];
                    acc[r] += kv.x*qv.x + kv.y*qv.y + kv.z*qv.z + kv.w*qv.w;
                }
            }
            #pragma unroll
            for (int r = 0; r < QT; r++)
                if (in[r]) sS[(r * HH + h) * SW + jj[r]] = acc[r] * scale;
        }
    }
    __syncthreads();

    // softmax: warp per (r,h) pair, 32 pairs over 16 warps
    {
        const int wid = tid >> 5, lane = tid & 31;
        for (int p = wid; p < QT * HH; p += (ATHR / 32)) {
            const int r = p >> 3;
            float* s = sS + p * SW;
            const int W = wd[r];
            float m = -1e30f;
            for (int i = lane; i < W; i += 32) m = fmaxf(m, s[i]);
            m = warpReduceMax(m);
            m = __shfl_sync(0xffffffffu, m, 0);
            float sum = 0.f;
            for (int i = lane; i < W; i += 32) {
                float e = __expf(s[i] - m);
                s[i] = e;
                sum += e;
            }
            sum = warpReduceSum(sum);
            if (lane == 0) sInv[p] = 1.0f / sum;
        }
    }
    __syncthreads();

    // attn_weights: mean over heads; zeros outside band
    #pragma unroll
    for (int r = 0; r < QT; r++) {
        float inv[HH];
        #pragma unroll
        for (int h = 0; h < HH; h++) inv[h] = sInv[r * HH + h];
        const size_t base = ((size_t)b * LQ + (qi0 + r)) * LK;
        for (int j = tid; j < LK; j += ATHR) {
            float val = 0.f;
            int idx = j - start[r];
            if (idx >= 0 && idx < wd[r]) {
                float t = 0.f;
                #pragma unroll
                for (int h = 0; h < HH; h++) t += sS[(r * HH + h) * SW + idx] * inv[h];
                val = t * 0.125f;  // 1/H
            }
            aw[base + j] = val;
        }
    }

    // context: each thread owns output o = tid for all QT rows
    {
        const int o = tid;
        const int h = o >> 6;
        float acc[QT];
        #pragma unroll
        for (int r = 0; r < QT; r++) acc[r] = 0.f;
        const float* vb = v + ((size_t)ustart * BB + b) * DD + o;

        #pragma unroll 4
        for (int idx = 0; idx < uW; idx++) {
            const float vv = vb[(size_t)idx * (BB * DD)];
            const int gk = ustart + idx;
            #pragma unroll
            for (int r = 0; r < QT; r++) {
                int j = gk - start[r];
                if (j >= 0 && j < wd[r])
                    acc[r] += sS[(r * HH + h) * SW + j] * vv;
            }
        }
        #pragma unroll
        for (int r = 0; r < QT; r++)
            ctx[((size_t)(qi0 + r) * BB + b) * DD + o] = acc[r] * sInv[r * HH + h];
    }
}

// ------------------------- launch -----------------------------------------
extern "C" void kernel_launch(void* const* d_in, const int* in_sizes, int n_in,
                              void* d_out, int out_size)
{
    const float* tgt    = (const float*)d_in[0];
    const float* memory = (const float*)d_in[1];
    const float* Wq = (const float*)d_in[2];  const float* bq = (const float*)d_in[3];
    const float* Wk = (const float*)d_in[4];  const float* bk = (const float*)d_in[5];
    const float* Wv = (const float*)d_in[6];  const float* bv = (const float*)d_in[7];
    const float* Wo = (const float*)d_in[8];  const float* bo = (const float*)d_in[9];
    const float* W1 = (const float*)d_in[10]; const float* b1 = (const float*)d_in[11];
    const float* W2 = (const float*)d_in[12]; const float* b2 = (const float*)d_in[13];
    const float* ln1w = (const float*)d_in[14]; const float* ln1b = (const float*)d_in[15];
    const float* ln2w = (const float*)d_in[16]; const float* ln2b = (const float*)d_in[17];
    const float* ln3w = (const float*)d_in[18]; const float* ln3b = (const float*)d_in[19];
    const float* ln4w = (const float*)d_in[20]; const float* ln4b = (const float*)d_in[21];

    float* out    = (float*)d_out;
    float* out_x  = out;
    float* out_aw = out + (size_t)LQ * BB * DD;

    float *t_, *m_, *q_, *k_, *v_, *ctx_, *x1_, *xn_, *ff1_;
    cudaGetSymbolAddress((void**)&t_,  g_t);
    cudaGetSymbolAddress((void**)&m_,  g_m);
    cudaGetSymbolAddress((void**)&q_,  g_q);
    cudaGetSymbolAddress((void**)&k_,  g_k);
    cudaGetSymbolAddress((void**)&v_,  g_v);
    cudaGetSymbolAddress((void**)&ctx_,g_ctx);
    cudaGetSymbolAddress((void**)&x1_, g_x1);
    cudaGetSymbolAddress((void**)&xn_, g_xn);
    cudaGetSymbolAddress((void**)&ff1_,g_ff1);

    static int attrDone = 0;
    if (!attrDone) {
        cudaFuncSetAttribute(attn_kernel, cudaFuncAttributeMaxDynamicSharedMemorySize, SMEM_ATTN);
        cudaFuncSetAttribute(gemm_tf32,  cudaFuncAttributeMaxDynamicSharedMemorySize, SMEM_GEMM);
        attrDone = 1;
    }

    // LN1 / LN2
    ln_kernel<<<LQ * BB, 256>>>(tgt,    ln1w, ln1b, t_);
    ln_kernel<<<LK * BB, 256>>>(memory, ln2w, ln2b, m_);

    // Q/K/V projections (tensor cores, 3xTF32)
    gemm_tf32<<<dim3(DD / GBN, (LQ * BB) / GBM), 256, SMEM_GEMM>>>(t_, Wq, bq, nullptr, q_, LQ * BB, DD, DD, 0);
    gemm_tf32<<<dim3(DD / GBN, (LK * BB) / GBM), 256, SMEM_GEMM>>>(m_, Wk, bk, nullptr, k_, LK * BB, DD, DD, 0);
    gemm_tf32<<<dim3(DD / GBN, (LK * BB) / GBM), 256, SMEM_GEMM>>>(m_, Wv, bv, nullptr, v_, LK * BB, DD, DD, 0);

    // fused banded attention
    attn_kernel<<<dim3(LQ / QT, BB), ATHR, SMEM_ATTN>>>(q_, k_, v_, ctx_, out_aw);

    // output projection + residual, LN3
    gemm_tf32<<<dim3(DD / GBN, (LQ * BB) / GBM), 256, SMEM_GEMM>>>(ctx_, Wo, bo, t_, x1_, LQ * BB, DD, DD, 0);
    ln_kernel<<<LQ * BB, 256>>>(x1_, ln3w, ln3b, xn_);

    // FFN
    gemm_tf32<<<dim3(DFF / GBN, (LQ * BB) / GBM), 256, SMEM_GEMM>>>(xn_, W1, b1, nullptr, ff1_, LQ * BB, DFF, DD, 1);
    gemm_tf32<<<dim3(DD / GBN, (LQ * BB) / GBM), 256, SMEM_GEMM>>>(ff1_, W2, b2, xn_, x1_, LQ * BB, DD, DFF, 0);

    // LN4 -> output x
    ln_kernel<<<LQ * BB, 256>>>(x1_, ln4w, ln4b, out_x);
}

// round 4
// speedup vs baseline: 1.5233x; 1.5233x over previous
#include <cuda_runtime.h>
#include <cuda_bf16.h>
#include <math.h>
#include <stdint.h>

// Problem constants
#define LQ   512
#define LK   4096
#define BB   4
#define DD   512
#define DFF  2048
#define HH   8
#define HD   64
#define LN_EPS 1e-5f

// ------------------------- scratch (device globals) -----------------------
__device__ float g_t  [LQ * BB * DD];
__device__ float g_m  [LK * BB * DD];
__device__ float g_q  [LQ * BB * DD];
__device__ float g_k  [LK * BB * DD];
__device__ float g_v  [LK * BB * DD];
__device__ float g_ctx[LQ * BB * DD];
__device__ float g_x1 [LQ * BB * DD];
__device__ float g_xn [LQ * BB * DD];
__device__ float g_ff1[LQ * BB * DFF];

// ------------------------- reductions ------------------------------------
__device__ __forceinline__ float warpReduceSum(float v) {
    #pragma unroll
    for (int o = 16; o > 0; o >>= 1) v += __shfl_down_sync(0xffffffffu, v, o);
    return v;
}
__device__ __forceinline__ float warpReduceMax(float v) {
    #pragma unroll
    for (int o = 16; o > 0; o >>= 1) v = fmaxf(v, __shfl_down_sync(0xffffffffu, v, o));
    return v;
}
__device__ __forceinline__ float blockReduceSum256(float v, float* shared) {
    __syncthreads();
    int lane = threadIdx.x & 31, wid = threadIdx.x >> 5;
    v = warpReduceSum(v);
    if (lane == 0) shared[wid] = v;
    __syncthreads();
    if (wid == 0) {
        float x = (lane < 8) ? shared[lane] : 0.f;
        #pragma unroll
        for (int o = 4; o > 0; o >>= 1) x += __shfl_down_sync(0xffffffffu, x, o);
        if (lane == 0) shared[0] = x;
    }
    __syncthreads();
    return shared[0];
}

// ------------------------- LayerNorm (row length 512) ---------------------
__global__ void ln_kernel(const float* __restrict__ in,
                          const float* __restrict__ w,
                          const float* __restrict__ b,
                          float* __restrict__ out)
{
    __shared__ float red[8];
    const int r = blockIdx.x;
    const float* xp = in + (size_t)r * DD;
    float* op = out + (size_t)r * DD;
    int t = threadIdx.x;

    float x0 = xp[t], x1 = xp[t + 256];
    float s = blockReduceSum256(x0 + x1, red);
    float mu = s * (1.0f / DD);
    float d0 = x0 - mu, d1 = x1 - mu;
    float ss = blockReduceSum256(d0 * d0 + d1 * d1, red);
    float rstd = rsqrtf(ss * (1.0f / DD) + LN_EPS);
    op[t]       = d0 * rstd * w[t]       + b[t];
    op[t + 256] = d1 * rstd * w[t + 256] + b[t + 256];
}

// ------------------------- bf16 helpers ------------------------------------
__device__ __forceinline__ uint32_t pk(__nv_bfloat16 lo, __nv_bfloat16 hi) {
    unsigned short a = __bfloat16_as_ushort(lo);
    unsigned short b = __bfloat16_as_ushort(hi);
    return (uint32_t)a | ((uint32_t)b << 16);
}
__device__ __forceinline__ void mma_bf16(float* d, const uint32_t* a, const uint32_t* b) {
    asm volatile(
        "mma.sync.aligned.m16n8k16.row.col.f32.bf16.bf16.f32 "
        "{%0,%1,%2,%3}, {%4,%5,%6,%7}, {%8,%9}, {%0,%1,%2,%3};"
        : "+f"(d[0]), "+f"(d[1]), "+f"(d[2]), "+f"(d[3])
        : "r"(a[0]), "r"(a[1]), "r"(a[2]), "r"(a[3]), "r"(b[0]), "r"(b[1]));
}

// ------------------------- GEMM: out[R,N] = A[R,K] @ W[N,K]^T + bias ------
// BMxBNx16 tiles, 256 threads = 8 warps (2Mx4N). 3xBF16 split:
// out = Ah*Bh + Ah*Bl + Al*Bh (error ~2^-17). Smem stores packed bf16 pairs,
// u32 row stride 12 -> conflict-free fragment loads, 8B-aligned uint2 stores.
#define SKS 12

template<int BM, int BN>
__global__ __launch_bounds__(256) void gemm_bf16x3(
        const float* __restrict__ A,
        const float* __restrict__ W,
        const float* __restrict__ bias,
        const float* __restrict__ res,
        float* __restrict__ out,
        int N, int K, int doRelu)
{
    constexpr int FM = BM / 32;   // m16 frags per warp (warp tile BM/2)
    constexpr int FN = BN / 32;   // n8 frags per warp (warp tile BN/4)
    constexpr int LA = BM / 64;   // float4 loads per thread for A tile
    constexpr int LB = BN / 64;

    extern __shared__ uint32_t usmem[];
    uint32_t* sAh = usmem;                    // [2][BM*SKS]
    uint32_t* sAl = sAh + 2 * BM * SKS;
    uint32_t* sBh = sAl + 2 * BM * SKS;       // [2][BN*SKS]
    uint32_t* sBl = sBh + 2 * BN * SKS;

    const int tid  = threadIdx.x;
    const int lane = tid & 31;
    const int warp = tid >> 5;
    const int g = lane >> 2, t = lane & 3;
    const int mW = (warp & 1) * (BM / 2);
    const int nW = (warp >> 1) * (BN / 4);
    const int rowBase = blockIdx.y * BM;
    const int colBase = blockIdx.x * BN;

    const int lr = tid >> 2;          // 0..63
    const int lc = (tid & 3) * 4;     // 0,4,8,12
    const float* Ag = A + (size_t)(rowBase + lr) * K + lc;
    const float* Wg = W + (size_t)(colBase + lr) * K + lc;

    float acc[FM][FN][4];
    #pragma unroll
    for (int i = 0; i < FM; i++)
        #pragma unroll
        for (int j = 0; j < FN; j++)
            #pragma unroll
            for (int c = 0; c < 4; c++) acc[i][j][c] = 0.f;

    float4 ra[LA], rw[LB];

    auto stage = [&](int buf) {
        #pragma unroll
        for (int i = 0; i < LA; i++) {
            float4 v = ra[i];
            __nv_bfloat16 h0 = __float2bfloat16(v.x), h1 = __float2bfloat16(v.y);
            __nv_bfloat16 h2 = __float2bfloat16(v.z), h3 = __float2bfloat16(v.w);
            __nv_bfloat16 l0 = __float2bfloat16(v.x - __bfloat162float(h0));
            __nv_bfloat16 l1 = __float2bfloat16(v.y - __bfloat162float(h1));
            __nv_bfloat16 l2 = __float2bfloat16(v.z - __bfloat162float(h2));
            __nv_bfloat16 l3 = __float2bfloat16(v.w - __bfloat162float(h3));
            int ofs = buf * BM * SKS + (lr + 64 * i) * SKS + (lc >> 1);
            *(uint2*)(sAh + ofs) = make_uint2(pk(h0, h1), pk(h2, h3));
            *(uint2*)(sAl + ofs) = make_uint2(pk(l0, l1), pk(l2, l3));
        }
        #pragma unroll
        for (int i = 0; i < LB; i++) {
            float4 v = rw[i];
            __nv_bfloat16 h0 = __float2bfloat16(v.x), h1 = __float2bfloat16(v.y);
            __nv_bfloat16 h2 = __float2bfloat16(v.z), h3 = __float2bfloat16(v.w);
            __nv_bfloat16 l0 = __float2bfloat16(v.x - __bfloat162float(h0));
            __nv_bfloat16 l1 = __float2bfloat16(v.y - __bfloat162float(h1));
            __nv_bfloat16 l2 = __float2bfloat16(v.z - __bfloat162float(h2));
            __nv_bfloat16 l3 = __float2bfloat16(v.w - __bfloat162float(h3));
            int ofs = buf * BN * SKS + (lr + 64 * i) * SKS + (lc >> 1);
            *(uint2*)(sBh + ofs) = make_uint2(pk(h0, h1), pk(h2, h3));
            *(uint2*)(sBl + ofs) = make_uint2(pk(l0, l1), pk(l2, l3));
        }
    };

    auto compute = [&](int buf) {
        const uint32_t* pAh = sAh + buf * BM * SKS;
        const uint32_t* pAl = sAl + buf * BM * SKS;
        const uint32_t* pBh = sBh + buf * BN * SKS;
        const uint32_t* pBl = sBl + buf * BN * SKS;
        uint32_t ah[FM][4], al[FM][4], bh[FN][2], bl[FN][2];
        #pragma unroll
        for (int mf = 0; mf < FM; mf++) {
            int r0 = mW + mf * 16 + g;
            ah[mf][0] = pAh[r0 * SKS + t];
            ah[mf][1] = pAh[(r0 + 8) * SKS + t];
            ah[mf][2] = pAh[r0 * SKS + t + 4];
            ah[mf][3] = pAh[(r0 + 8) * SKS + t + 4];
            al[mf][0] = pAl[r0 * SKS + t];
            al[mf][1] = pAl[(r0 + 8) * SKS + t];
            al[mf][2] = pAl[r0 * SKS + t + 4];
            al[mf][3] = pAl[(r0 + 8) * SKS + t + 4];
        }
        #pragma unroll
        for (int nf = 0; nf < FN; nf++) {
            int c0 = nW + nf * 8 + g;
            bh[nf][0] = pBh[c0 * SKS + t];
            bh[nf][1] = pBh[c0 * SKS + t + 4];
            bl[nf][0] = pBl[c0 * SKS + t];
            bl[nf][1] = pBl[c0 * SKS + t + 4];
        }
        #pragma unroll
        for (int mf = 0; mf < FM; mf++)
            #pragma unroll
            for (int nf = 0; nf < FN; nf++) {
                mma_bf16(acc[mf][nf], ah[mf], bh[nf]);
                mma_bf16(acc[mf][nf], ah[mf], bl[nf]);
                mma_bf16(acc[mf][nf], al[mf], bh[nf]);
            }
    };

    // prologue
    #pragma unroll
    for (int i = 0; i < LA; i++) ra[i] = *(const float4*)(Ag + (size_t)i * 64 * K);
    #pragma unroll
    for (int i = 0; i < LB; i++) rw[i] = *(const float4*)(Wg + (size_t)i * 64 * K);
    stage(0);
    __syncthreads();

    const int nT = K / 16;
    int buf = 0;
    for (int tt = 1; tt < nT; tt++) {
        #pragma unroll
        for (int i = 0; i < LA; i++) ra[i] = *(const float4*)(Ag + (size_t)i * 64 * K + tt * 16);
        #pragma unroll
        for (int i = 0; i < LB; i++) rw[i] = *(const float4*)(Wg + (size_t)i * 64 * K + tt * 16);
        compute(buf);
        stage(buf ^ 1);
        __syncthreads();
        buf ^= 1;
    }
    compute(buf);

    // epilogue: c0,c1 -> (row, 2t/2t+1); c2,c3 -> (row+8, ...)
    #pragma unroll
    for (int mf = 0; mf < FM; mf++) {
        int row0 = rowBase + mW + mf * 16 + g;
        #pragma unroll
        for (int nf = 0; nf < FN; nf++) {
            int col = colBase + nW + nf * 8 + 2 * t;
            float2 bb = *(const float2*)(bias + col);
            float2 v0, v1;
            v0.x = acc[mf][nf][0] + bb.x; v0.y = acc[mf][nf][1] + bb.y;
            v1.x = acc[mf][nf][2] + bb.x; v1.y = acc[mf][nf][3] + bb.y;
            if (doRelu) {
                v0.x = fmaxf(v0.x, 0.f); v0.y = fmaxf(v0.y, 0.f);
                v1.x = fmaxf(v1.x, 0.f); v1.y = fmaxf(v1.y, 0.f);
            }
            if (res) {
                float2 r0 = *(const float2*)(res + (size_t)row0 * N + col);
                float2 r1 = *(const float2*)(res + (size_t)(row0 + 8) * N + col);
                v0.x += r0.x; v0.y += r0.y;
                v1.x += r1.x; v1.y += r1.y;
            }
            *(float2*)(out + (size_t)row0 * N + col) = v0;
            *(float2*)(out + (size_t)(row0 + 8) * N + col) = v1;
        }
    }
}

#define SMEM_G128 (16 * SKS * (128 + 128))   // 49152 bytes
#define SMEM_G64  (16 * SKS * (64 + 64))     // 24576 bytes

// ------------------------- fused banded attention (R2 version) -------------
// QT query rows per block, all 8 heads. 256 threads, dynamic smem.
#define QT 4
#define SW 832
#define SMEM_ATTN ((QT*DD + QT*HH*SW + QT*HH) * 4)

__global__ __launch_bounds__(256) void attn_kernel(
        const float* __restrict__ q,
        const float* __restrict__ k,
        const float* __restrict__ v,
        float* __restrict__ ctx,
        float* __restrict__ aw)
{
    extern __shared__ float smem[];
    float* sQ   = smem;                    // QT*DD
    float* sS   = smem + QT * DD;          // QT*HH*SW
    float* sInv = sS + QT * HH * SW;       // QT*HH

    const int qi0 = blockIdx.x * QT;
    const int b   = blockIdx.y;
    const int tid = threadIdx.x;

    int start[QT], wd[QT];
    #pragma unroll
    for (int r = 0; r < QT; r++) {
        int qi = qi0 + r;
        if (qi >= 409) { start[r] = 3268; wd[r] = 828; }
        else           { start[r] = qi * 8; wd[r] = 827; }
    }
    const int ustart = start[0];
    const int uend   = start[QT-1] + wd[QT-1];
    const int uW     = uend - ustart;

    for (int i = tid; i < QT * DD; i += 256) {
        int r = i / DD, c = i % DD;
        sQ[i] = q[((size_t)(qi0 + r) * BB + b) * DD + c];
    }
    __syncthreads();

    const float scale = 0.125f;  // 1/sqrt(64)

    // scores over the union band
    for (int idx = tid; idx < uW; idx += 256) {
        const int gk = ustart + idx;
        const float4* kp = (const float4*)(k + ((size_t)gk * BB + b) * DD);
        int jj[QT]; bool in[QT];
        #pragma unroll
        for (int r = 0; r < QT; r++) {
            jj[r] = gk - start[r];
            in[r] = (jj[r] >= 0) && (jj[r] < wd[r]);
        }
        #pragma unroll
        for (int h = 0; h < HH; h++) {
            float acc[QT];
            #pragma unroll
            for (int r = 0; r < QT; r++) acc[r] = 0.f;
            #pragma unroll
            for (int c = 0; c < 16; c++) {
                float4 kv = kp[h * 16 + c];
                #pragma unroll
                for (int r = 0; r < QT; r++) {
                    float4 qv = ((const float4*)(sQ + r * DD))[h * 16 + c];
                    acc[r] += kv.x*qv.x + kv.y*qv.y + kv.z*qv.z + kv.w*qv.w;
                }
            }
            #pragma unroll
            for (int r = 0; r < QT; r++)
                if (in[r]) sS[(r * HH + h) * SW + jj[r]] = acc[r] * scale;
        }
    }
    __syncthreads();

    // softmax: warp per (r,h) pair
    {
        const int wid = tid >> 5, lane = tid & 31;
        for (int p = wid; p < QT * HH; p += 8) {
            const int r = p >> 3;
            float* s = sS + p * SW;
            const int W = wd[r];
            float m = -1e30f;
            for (int i = lane; i < W; i += 32) m = fmaxf(m, s[i]);
            m = warpReduceMax(m);
            m = __shfl_sync(0xffffffffu, m, 0);
            float sum = 0.f;
            for (int i = lane; i < W; i += 32) {
                float e = __expf(s[i] - m);
                s[i] = e;
                sum += e;
            }
            sum = warpReduceSum(sum);
            if (lane == 0) sInv[p] = 1.0f / sum;
        }
    }
    __syncthreads();

    // attn_weights: mean over heads; zeros outside band
    #pragma unroll
    for (int r = 0; r < QT; r++) {
        float inv[HH];
        #pragma unroll
        for (int h = 0; h < HH; h++) inv[h] = sInv[r * HH + h];
        const size_t base = ((size_t)b * LQ + (qi0 + r)) * LK;
        for (int j = tid; j < LK; j += 256) {
            float val = 0.f;
            int idx = j - start[r];
            if (idx >= 0 && idx < wd[r]) {
                float t = 0.f;
                #pragma unroll
                for (int h = 0; h < HH; h++) t += sS[(r * HH + h) * SW + idx] * inv[h];
                val = t * 0.125f;  // 1/H
            }
            aw[base + j] = val;
        }
    }

    // context: each thread owns outputs o=tid and o=tid+256 for all QT rows
    {
        const int o1 = tid, o2 = tid + 256;
        const int h1 = o1 >> 6, h2 = o2 >> 6;
        float acc1[QT], acc2[QT];
        #pragma unroll
        for (int r = 0; r < QT; r++) { acc1[r] = 0.f; acc2[r] = 0.f; }
        const float* vb = v + ((size_t)ustart * BB + b) * DD;

        #pragma unroll 4
        for (int idx = 0; idx < uW; idx++) {
            const float v1 = vb[(size_t)idx * (BB * DD) + o1];
            const float v2 = vb[(size_t)idx * (BB * DD) + o2];
            const int gk = ustart + idx;
            #pragma unroll
            for (int r = 0; r < QT; r++) {
                int j = gk - start[r];
                if (j >= 0 && j < wd[r]) {
                    acc1[r] += sS[(r * HH + h1) * SW + j] * v1;
                    acc2[r] += sS[(r * HH + h2) * SW + j] * v2;
                }
            }
        }
        #pragma unroll
        for (int r = 0; r < QT; r++) {
            ctx[((size_t)(qi0 + r) * BB + b) * DD + o1] = acc1[r] * sInv[r * HH + h1];
            ctx[((size_t)(qi0 + r) * BB + b) * DD + o2] = acc2[r] * sInv[r * HH + h2];
        }
    }
}

// ------------------------- launch -----------------------------------------
extern "C" void kernel_launch(void* const* d_in, const int* in_sizes, int n_in,
                              void* d_out, int out_size)
{
    const float* tgt    = (const float*)d_in[0];
    const float* memory = (const float*)d_in[1];
    const float* Wq = (const float*)d_in[2];  const float* bq = (const float*)d_in[3];
    const float* Wk = (const float*)d_in[4];  const float* bk = (const float*)d_in[5];
    const float* Wv = (const float*)d_in[6];  const float* bv = (const float*)d_in[7];
    const float* Wo = (const float*)d_in[8];  const float* bo = (const float*)d_in[9];
    const float* W1 = (const float*)d_in[10]; const float* b1 = (const float*)d_in[11];
    const float* W2 = (const float*)d_in[12]; const float* b2 = (const float*)d_in[13];
    const float* ln1w = (const float*)d_in[14]; const float* ln1b = (const float*)d_in[15];
    const float* ln2w = (const float*)d_in[16]; const float* ln2b = (const float*)d_in[17];
    const float* ln3w = (const float*)d_in[18]; const float* ln3b = (const float*)d_in[19];
    const float* ln4w = (const float*)d_in[20]; const float* ln4b = (const float*)d_in[21];

    float* out    = (float*)d_out;
    float* out_x  = out;
    float* out_aw = out + (size_t)LQ * BB * DD;

    float *t_, *m_, *q_, *k_, *v_, *ctx_, *x1_, *xn_, *ff1_;
    cudaGetSymbolAddress((void**)&t_,  g_t);
    cudaGetSymbolAddress((void**)&m_,  g_m);
    cudaGetSymbolAddress((void**)&q_,  g_q);
    cudaGetSymbolAddress((void**)&k_,  g_k);
    cudaGetSymbolAddress((void**)&v_,  g_v);
    cudaGetSymbolAddress((void**)&ctx_,g_ctx);
    cudaGetSymbolAddress((void**)&x1_, g_x1);
    cudaGetSymbolAddress((void**)&xn_, g_xn);
    cudaGetSymbolAddress((void**)&ff1_,g_ff1);

    cudaFuncSetAttribute(attn_kernel, cudaFuncAttributeMaxDynamicSharedMemorySize, SMEM_ATTN);
    cudaFuncSetAttribute(gemm_bf16x3<128,128>, cudaFuncAttributeMaxDynamicSharedMemorySize, SMEM_G128);
    cudaFuncSetAttribute(gemm_bf16x3<64,64>,   cudaFuncAttributeMaxDynamicSharedMemorySize, SMEM_G64);

    // LN1 / LN2
    ln_kernel<<<LQ * BB, 256>>>(tgt,    ln1w, ln1b, t_);
    ln_kernel<<<LK * BB, 256>>>(memory, ln2w, ln2b, m_);

    // Q/K/V projections
    gemm_bf16x3<64,64>  <<<dim3(DD / 64,  (LQ * BB) / 64),  256, SMEM_G64 >>>(t_, Wq, bq, nullptr, q_, DD, DD, 0);
    gemm_bf16x3<128,128><<<dim3(DD / 128, (LK * BB) / 128), 256, SMEM_G128>>>(m_, Wk, bk, nullptr, k_, DD, DD, 0);
    gemm_bf16x3<128,128><<<dim3(DD / 128, (LK * BB) / 128), 256, SMEM_G128>>>(m_, Wv, bv, nullptr, v_, DD, DD, 0);

    // fused banded attention
    attn_kernel<<<dim3(LQ / QT, BB), 256, SMEM_ATTN>>>(q_, k_, v_, ctx_, out_aw);

    // output projection + residual, LN3
    gemm_bf16x3<64,64><<<dim3(DD / 64, (LQ * BB) / 64), 256, SMEM_G64>>>(ctx_, Wo, bo, t_, x1_, DD, DD, 0);
    ln_kernel<<<LQ * BB, 256>>>(x1_, ln3w, ln3b, xn_);

    // FFN
    gemm_bf16x3<128,128><<<dim3(DFF / 128, (LQ * BB) / 128), 256, SMEM_G128>>>(xn_, W1, b1, nullptr, ff1_, DFF, DD, 1);
    gemm_bf16x3<64,64>  <<<dim3(DD / 64,   (LQ * BB) / 64),  256, SMEM_G64 >>>(ff1_, W2, b2, xn_, x1_, DD, DFF, 0);

    // LN4 -> output x
    ln_kernel<<<LQ * BB, 256>>>(x1_, ln4w, ln4b, out_x);
}

// round 5
// speedup vs baseline: 1.9568x; 1.2845x over previous
#include <cuda_runtime.h>
#include <cuda_bf16.h>
#include <math.h>
#include <stdint.h>

// Problem constants
#define LQ   512
#define LK   4096
#define BB   4
#define DD   512
#define DFF  2048
#define HH   8
#define HD   64
#define LN_EPS 1e-5f

// ------------------------- scratch (device globals) -----------------------
__device__ float g_t  [LQ * BB * DD];
__device__ float g_m  [LK * BB * DD];
__device__ float g_q  [LQ * BB * DD];
__device__ float g_k  [LK * BB * DD];
__device__ float g_v  [LK * BB * DD];
__device__ float g_ctx[LQ * BB * DD];
__device__ float g_x1 [LQ * BB * DD];
__device__ float g_xn [LQ * BB * DD];
__device__ float g_ff1[LQ * BB * DFF];

// ------------------------- reductions ------------------------------------
__device__ __forceinline__ float warpReduceSum(float v) {
    #pragma unroll
    for (int o = 16; o > 0; o >>= 1) v += __shfl_down_sync(0xffffffffu, v, o);
    return v;
}
__device__ __forceinline__ float blockReduceSum256(float v, float* shared) {
    __syncthreads();
    int lane = threadIdx.x & 31, wid = threadIdx.x >> 5;
    v = warpReduceSum(v);
    if (lane == 0) shared[wid] = v;
    __syncthreads();
    if (wid == 0) {
        float x = (lane < 8) ? shared[lane] : 0.f;
        #pragma unroll
        for (int o = 4; o > 0; o >>= 1) x += __shfl_down_sync(0xffffffffu, x, o);
        if (lane == 0) shared[0] = x;
    }
    __syncthreads();
    return shared[0];
}

// ------------------------- LayerNorm (row length 512) ---------------------
__global__ void ln_kernel(const float* __restrict__ in,
                          const float* __restrict__ w,
                          const float* __restrict__ b,
                          float* __restrict__ out)
{
    __shared__ float red[8];
    const int r = blockIdx.x;
    const float* xp = in + (size_t)r * DD;
    float* op = out + (size_t)r * DD;
    int t = threadIdx.x;

    float x0 = xp[t], x1 = xp[t + 256];
    float s = blockReduceSum256(x0 + x1, red);
    float mu = s * (1.0f / DD);
    float d0 = x0 - mu, d1 = x1 - mu;
    float ss = blockReduceSum256(d0 * d0 + d1 * d1, red);
    float rstd = rsqrtf(ss * (1.0f / DD) + LN_EPS);
    op[t]       = d0 * rstd * w[t]       + b[t];
    op[t + 256] = d1 * rstd * w[t + 256] + b[t + 256];
}

// ------------------------- bf16 helpers ------------------------------------
__device__ __forceinline__ uint32_t pk(__nv_bfloat16 lo, __nv_bfloat16 hi) {
    unsigned short a = __bfloat16_as_ushort(lo);
    unsigned short b = __bfloat16_as_ushort(hi);
    return (uint32_t)a | ((uint32_t)b << 16);
}
__device__ __forceinline__ void split2(float2 f, uint32_t& h, uint32_t& l) {
    __nv_bfloat16 h0 = __float2bfloat16(f.x), h1 = __float2bfloat16(f.y);
    __nv_bfloat16 l0 = __float2bfloat16(f.x - __bfloat162float(h0));
    __nv_bfloat16 l1 = __float2bfloat16(f.y - __bfloat162float(h1));
    h = pk(h0, h1); l = pk(l0, l1);
}
__device__ __forceinline__ void mma_bf16(float* d, const uint32_t* a, const uint32_t* b) {
    asm volatile(
        "mma.sync.aligned.m16n8k16.row.col.f32.bf16.bf16.f32 "
        "{%0,%1,%2,%3}, {%4,%5,%6,%7}, {%8,%9}, {%0,%1,%2,%3};"
        : "+f"(d[0]), "+f"(d[1]), "+f"(d[2]), "+f"(d[3])
        : "r"(a[0]), "r"(a[1]), "r"(a[2]), "r"(a[3]), "r"(b[0]), "r"(b[1]));
}

// ------------------------- GEMM: out[R,N] = A[R,K] @ W[N,K]^T + bias ------
#define SKS 12

template<int BM, int BN>
__global__ __launch_bounds__(256) void gemm_bf16x3(
        const float* __restrict__ A,
        const float* __restrict__ W,
        const float* __restrict__ bias,
        const float* __restrict__ res,
        float* __restrict__ out,
        int N, int K, int doRelu)
{
    constexpr int FM = BM / 32;
    constexpr int FN = BN / 32;
    constexpr int LA = BM / 64;
    constexpr int LB = BN / 64;

    extern __shared__ uint32_t usmem[];
    uint32_t* sAh = usmem;
    uint32_t* sAl = sAh + 2 * BM * SKS;
    uint32_t* sBh = sAl + 2 * BM * SKS;
    uint32_t* sBl = sBh + 2 * BN * SKS;

    const int tid  = threadIdx.x;
    const int lane = tid & 31;
    const int warp = tid >> 5;
    const int g = lane >> 2, t = lane & 3;
    const int mW = (warp & 1) * (BM / 2);
    const int nW = (warp >> 1) * (BN / 4);
    const int rowBase = blockIdx.y * BM;
    const int colBase = blockIdx.x * BN;

    const int lr = tid >> 2;
    const int lc = (tid & 3) * 4;
    const float* Ag = A + (size_t)(rowBase + lr) * K + lc;
    const float* Wg = W + (size_t)(colBase + lr) * K + lc;

    float acc[FM][FN][4];
    #pragma unroll
    for (int i = 0; i < FM; i++)
        #pragma unroll
        for (int j = 0; j < FN; j++)
            #pragma unroll
            for (int c = 0; c < 4; c++) acc[i][j][c] = 0.f;

    float4 ra[LA], rw[LB];

    auto stage = [&](int buf) {
        #pragma unroll
        for (int i = 0; i < LA; i++) {
            float4 v = ra[i];
            uint32_t h0, l0, h1, l1;
            split2(make_float2(v.x, v.y), h0, l0);
            split2(make_float2(v.z, v.w), h1, l1);
            int ofs = buf * BM * SKS + (lr + 64 * i) * SKS + (lc >> 1);
            *(uint2*)(sAh + ofs) = make_uint2(h0, h1);
            *(uint2*)(sAl + ofs) = make_uint2(l0, l1);
        }
        #pragma unroll
        for (int i = 0; i < LB; i++) {
            float4 v = rw[i];
            uint32_t h0, l0, h1, l1;
            split2(make_float2(v.x, v.y), h0, l0);
            split2(make_float2(v.z, v.w), h1, l1);
            int ofs = buf * BN * SKS + (lr + 64 * i) * SKS + (lc >> 1);
            *(uint2*)(sBh + ofs) = make_uint2(h0, h1);
            *(uint2*)(sBl + ofs) = make_uint2(l0, l1);
        }
    };

    auto compute = [&](int buf) {
        const uint32_t* pAh = sAh + buf * BM * SKS;
        const uint32_t* pAl = sAl + buf * BM * SKS;
        const uint32_t* pBh = sBh + buf * BN * SKS;
        const uint32_t* pBl = sBl + buf * BN * SKS;
        uint32_t ah[FM][4], al[FM][4], bh[FN][2], bl[FN][2];
        #pragma unroll
        for (int mf = 0; mf < FM; mf++) {
            int r0 = mW + mf * 16 + g;
            ah[mf][0] = pAh[r0 * SKS + t];
            ah[mf][1] = pAh[(r0 + 8) * SKS + t];
            ah[mf][2] = pAh[r0 * SKS + t + 4];
            ah[mf][3] = pAh[(r0 + 8) * SKS + t + 4];
            al[mf][0] = pAl[r0 * SKS + t];
            al[mf][1] = pAl[(r0 + 8) * SKS + t];
            al[mf][2] = pAl[r0 * SKS + t + 4];
            al[mf][3] = pAl[(r0 + 8) * SKS + t + 4];
        }
        #pragma unroll
        for (int nf = 0; nf < FN; nf++) {
            int c0 = nW + nf * 8 + g;
            bh[nf][0] = pBh[c0 * SKS + t];
            bh[nf][1] = pBh[c0 * SKS + t + 4];
            bl[nf][0] = pBl[c0 * SKS + t];
            bl[nf][1] = pBl[c0 * SKS + t + 4];
        }
        #pragma unroll
        for (int mf = 0; mf < FM; mf++)
            #pragma unroll
            for (int nf = 0; nf < FN; nf++) {
                mma_bf16(acc[mf][nf], ah[mf], bh[nf]);
                mma_bf16(acc[mf][nf], ah[mf], bl[nf]);
                mma_bf16(acc[mf][nf], al[mf], bh[nf]);
            }
    };

    #pragma unroll
    for (int i = 0; i < LA; i++) ra[i] = *(const float4*)(Ag + (size_t)i * 64 * K);
    #pragma unroll
    for (int i = 0; i < LB; i++) rw[i] = *(const float4*)(Wg + (size_t)i * 64 * K);
    stage(0);
    __syncthreads();

    const int nT = K / 16;
    int buf = 0;
    for (int tt = 1; tt < nT; tt++) {
        #pragma unroll
        for (int i = 0; i < LA; i++) ra[i] = *(const float4*)(Ag + (size_t)i * 64 * K + tt * 16);
        #pragma unroll
        for (int i = 0; i < LB; i++) rw[i] = *(const float4*)(Wg + (size_t)i * 64 * K + tt * 16);
        compute(buf);
        stage(buf ^ 1);
        __syncthreads();
        buf ^= 1;
    }
    compute(buf);

    #pragma unroll
    for (int mf = 0; mf < FM; mf++) {
        int row0 = rowBase + mW + mf * 16 + g;
        #pragma unroll
        for (int nf = 0; nf < FN; nf++) {
            int col = colBase + nW + nf * 8 + 2 * t;
            float2 bb = *(const float2*)(bias + col);
            float2 v0, v1;
            v0.x = acc[mf][nf][0] + bb.x; v0.y = acc[mf][nf][1] + bb.y;
            v1.x = acc[mf][nf][2] + bb.x; v1.y = acc[mf][nf][3] + bb.y;
            if (doRelu) {
                v0.x = fmaxf(v0.x, 0.f); v0.y = fmaxf(v0.y, 0.f);
                v1.x = fmaxf(v1.x, 0.f); v1.y = fmaxf(v1.y, 0.f);
            }
            if (res) {
                float2 r0 = *(const float2*)(res + (size_t)row0 * N + col);
                float2 r1 = *(const float2*)(res + (size_t)(row0 + 8) * N + col);
                v0.x += r0.x; v0.y += r0.y;
                v1.x += r1.x; v1.y += r1.y;
            }
            *(float2*)(out + (size_t)row0 * N + col) = v0;
            *(float2*)(out + (size_t)(row0 + 8) * N + col) = v1;
        }
    }
}

#define SMEM_G128 (16 * SKS * (128 + 128))
#define SMEM_G64  (16 * SKS * (64 + 64))

// ------------------------- MMA banded attention ----------------------------
// 16 q-rows per block, grid (32, 4). Per head: scores via bf16x3 mma
// (Q staged in smem, K fragments from global), softmax + head-mean in smem,
// context via bf16x3 mma (P from smem, V fragments from global).
#define SQS 260          // Q smem stride (u32 pairs), conflict-free a-frags
#define SSW 968          // S / awsum stride (f32)
#define SMEM_ATTN ((2 * 16 * SQS + 2 * 16 * SSW + 16) * 4)

__device__ __forceinline__ int band_start(int qi) { return (qi >= 409) ? 3268 : qi * 8; }
__device__ __forceinline__ int band_wd(int qi)    { return (qi >= 409) ? 828  : 827; }

__global__ __launch_bounds__(256) void attn_mma(
        const float* __restrict__ q,
        const float* __restrict__ k,
        const float* __restrict__ v,
        float* __restrict__ ctx,
        float* __restrict__ aw)
{
    extern __shared__ uint32_t sm[];
    uint32_t* sQh = sm;                         // [16][SQS]
    uint32_t* sQl = sQh + 16 * SQS;
    float*    sS  = (float*)(sQl + 16 * SQS);   // [16][SSW]
    float*    aws = sS + 16 * SSW;              // [16][SSW]
    float*    sInvH = aws + 16 * SSW;           // [16]

    const int qi0 = blockIdx.x * 16;
    const int b   = blockIdx.y;
    const int tid = threadIdx.x;
    const int lane = tid & 31;
    const int warp = tid >> 5;
    const int g = lane >> 2, t = lane & 3;

    const int ustart = band_start(qi0);
    const int uend   = band_start(qi0 + 15) + band_wd(qi0 + 15);
    const int uW     = uend - ustart;
    const int ngroups = (uW + 7) >> 3;
    const int KPAD    = ((uW + 15) >> 4) << 4;

    // stage Q (scaled by 1/8) as bf16 hi/lo pairs
    for (int i = tid; i < 16 * 256; i += 256) {
        int r = i >> 8, c = i & 255;
        float2 f = *(const float2*)(q + ((size_t)(qi0 + r) * BB + b) * DD + 2 * c);
        f.x *= 0.125f; f.y *= 0.125f;
        uint32_t h, l;
        split2(f, h, l);
        sQh[r * SQS + c] = h;
        sQl[r * SQS + c] = l;
    }

    for (int h = 0; h < HH; h++) {
        __syncthreads();   // sS free (prev context done) / Q staged

        // hoist Q a-frags for this head
        uint32_t qah[4][4], qal[4][4];
        #pragma unroll
        for (int ks = 0; ks < 4; ks++) {
            int base = g * SQS + h * 32 + ks * 8 + t;
            qah[ks][0] = sQh[base];
            qah[ks][1] = sQh[base + 8 * SQS];
            qah[ks][2] = sQh[base + 4];
            qah[ks][3] = sQh[base + 8 * SQS + 4];
            qal[ks][0] = sQl[base];
            qal[ks][1] = sQl[base + 8 * SQS];
            qal[ks][2] = sQl[base + 4];
            qal[ks][3] = sQl[base + 8 * SQS + 4];
        }

        // ---- scores: warp handles key-groups warp, warp+8, ... ----
        for (int grp = warp; grp < ngroups; grp += 8) {
            int key = ustart + grp * 8 + g;
            if (key > LK - 1) key = LK - 1;
            const float* kp = k + ((size_t)key * BB + b) * DD + h * 64;
            float acc[4] = {0.f, 0.f, 0.f, 0.f};
            #pragma unroll
            for (int ks = 0; ks < 4; ks++) {
                float2 f0 = *(const float2*)(kp + ks * 16 + 2 * t);
                float2 f1 = *(const float2*)(kp + ks * 16 + 2 * t + 8);
                uint32_t bh[2], bl[2];
                split2(f0, bh[0], bl[0]);
                split2(f1, bh[1], bl[1]);
                mma_bf16(acc, qah[ks], bh);
                mma_bf16(acc, qah[ks], bl);
                mma_bf16(acc, qal[ks], bh);
            }
            *(float2*)(sS + g * SSW + grp * 8 + 2 * t)       = make_float2(acc[0], acc[1]);
            *(float2*)(sS + (g + 8) * SSW + grp * 8 + 2 * t) = make_float2(acc[2], acc[3]);
        }
        __syncthreads();

        // ---- softmax + head-mean accumulation + zero padding ----
        #pragma unroll
        for (int rr = 0; rr < 2; rr++) {
            const int r  = warp + rr * 8;
            const int qi = qi0 + r;
            const int j0 = band_start(qi) - ustart;
            const int W  = band_wd(qi);
            float* srow = sS + r * SSW;

            float m = -1e30f;
            for (int i = j0 + lane; i < j0 + W; i += 32) m = fmaxf(m, srow[i]);
            #pragma unroll
            for (int o = 16; o > 0; o >>= 1) m = fmaxf(m, __shfl_xor_sync(0xffffffffu, m, o));
            float sum = 0.f;
            for (int i = j0 + lane; i < j0 + W; i += 32) {
                float e = __expf(srow[i] - m);
                srow[i] = e;
                sum += e;
            }
            #pragma unroll
            for (int o = 16; o > 0; o >>= 1) sum += __shfl_xor_sync(0xffffffffu, sum, o);
            float inv = 1.0f / sum;
            if (lane == 0) sInvH[r] = inv;

            float cc = inv * 0.125f;   // 1/H
            float* arow = aws + r * SSW;
            if (h == 0) {
                for (int i = j0 + lane; i < j0 + W; i += 32) arow[i] = srow[i] * cc;
            } else {
                for (int i = j0 + lane; i < j0 + W; i += 32) arow[i] += srow[i] * cc;
            }
            for (int i = lane; i < j0; i += 32) srow[i] = 0.f;
            for (int i = j0 + W + lane; i < KPAD; i += 32) srow[i] = 0.f;
        }
        __syncthreads();

        // ---- context: warp owns dims h*64 + warp*8 .. +7 ----
        {
            const int dimBase = h * 64 + warp * 8;
            float cacc[4] = {0.f, 0.f, 0.f, 0.f};
            const int nchunks = KPAD >> 4;
            const float* vcol = v + (size_t)b * DD + dimBase + g;
            for (int ck = 0; ck < nchunks; ck++) {
                const float* pr0 = sS + g * SSW + ck * 16 + 2 * t;
                const float* pr8 = sS + (g + 8) * SSW + ck * 16 + 2 * t;
                float2 p0 = *(const float2*)(pr0);
                float2 p2 = *(const float2*)(pr8);
                float2 p1 = *(const float2*)(pr0 + 8);
                float2 p3 = *(const float2*)(pr8 + 8);
                uint32_t ah[4], al[4];
                split2(p0, ah[0], al[0]);
                split2(p2, ah[1], al[1]);
                split2(p1, ah[2], al[2]);
                split2(p3, ah[3], al[3]);

                int kb = ustart + ck * 16 + 2 * t;
                int k0 = kb;     if (k0 > LK - 1) k0 = LK - 1;
                int k1 = kb + 1; if (k1 > LK - 1) k1 = LK - 1;
                int k8 = kb + 8; if (k8 > LK - 1) k8 = LK - 1;
                int k9 = kb + 9; if (k9 > LK - 1) k9 = LK - 1;
                float2 fv0 = make_float2(vcol[(size_t)k0 * (BB * DD)], vcol[(size_t)k1 * (BB * DD)]);
                float2 fv1 = make_float2(vcol[(size_t)k8 * (BB * DD)], vcol[(size_t)k9 * (BB * DD)]);
                uint32_t bh[2], bl[2];
                split2(fv0, bh[0], bl[0]);
                split2(fv1, bh[1], bl[1]);

                mma_bf16(cacc, ah, bh);
                mma_bf16(cacc, ah, bl);
                mma_bf16(cacc, al, bh);
            }
            float inv0 = sInvH[g];
            float inv1 = sInvH[g + 8];
            *(float2*)(ctx + ((size_t)(qi0 + g) * BB + b) * DD + dimBase + 2 * t) =
                make_float2(cacc[0] * inv0, cacc[1] * inv0);
            *(float2*)(ctx + ((size_t)(qi0 + g + 8) * BB + b) * DD + dimBase + 2 * t) =
                make_float2(cacc[2] * inv1, cacc[3] * inv1);
        }
    }
    __syncthreads();

    // ---- final attn_weights write (zeros outside band) ----
    for (int i = tid; i < 16 * 1024; i += 256) {
        int r  = i >> 10;
        int c  = (i & 1023) << 2;
        int qi = qi0 + r;
        int s0 = band_start(qi);
        int W  = band_wd(qi);
        const float* arow = aws + r * SSW;
        float4 o;
        {
            int j = c + 0, jj = j - s0;
            o.x = (jj >= 0 && jj < W) ? arow[j - ustart] : 0.f;
            j = c + 1; jj = j - s0;
            o.y = (jj >= 0 && jj < W) ? arow[j - ustart] : 0.f;
            j = c + 2; jj = j - s0;
            o.z = (jj >= 0 && jj < W) ? arow[j - ustart] : 0.f;
            j = c + 3; jj = j - s0;
            o.w = (jj >= 0 && jj < W) ? arow[j - ustart] : 0.f;
        }
        *(float4*)(aw + ((size_t)b * LQ + qi) * LK + c) = o;
    }
}

// ------------------------- launch -----------------------------------------
extern "C" void kernel_launch(void* const* d_in, const int* in_sizes, int n_in,
                              void* d_out, int out_size)
{
    const float* tgt    = (const float*)d_in[0];
    const float* memory = (const float*)d_in[1];
    const float* Wq = (const float*)d_in[2];  const float* bq = (const float*)d_in[3];
    const float* Wk = (const float*)d_in[4];  const float* bk = (const float*)d_in[5];
    const float* Wv = (const float*)d_in[6];  const float* bv = (const float*)d_in[7];
    const float* Wo = (const float*)d_in[8];  const float* bo = (const float*)d_in[9];
    const float* W1 = (const float*)d_in[10]; const float* b1 = (const float*)d_in[11];
    const float* W2 = (const float*)d_in[12]; const float* b2 = (const float*)d_in[13];
    const float* ln1w = (const float*)d_in[14]; const float* ln1b = (const float*)d_in[15];
    const float* ln2w = (const float*)d_in[16]; const float* ln2b = (const float*)d_in[17];
    const float* ln3w = (const float*)d_in[18]; const float* ln3b = (const float*)d_in[19];
    const float* ln4w = (const float*)d_in[20]; const float* ln4b = (const float*)d_in[21];

    float* out    = (float*)d_out;
    float* out_x  = out;
    float* out_aw = out + (size_t)LQ * BB * DD;

    float *t_, *m_, *q_, *k_, *v_, *ctx_, *x1_, *xn_, *ff1_;
    cudaGetSymbolAddress((void**)&t_,  g_t);
    cudaGetSymbolAddress((void**)&m_,  g_m);
    cudaGetSymbolAddress((void**)&q_,  g_q);
    cudaGetSymbolAddress((void**)&k_,  g_k);
    cudaGetSymbolAddress((void**)&v_,  g_v);
    cudaGetSymbolAddress((void**)&ctx_,g_ctx);
    cudaGetSymbolAddress((void**)&x1_, g_x1);
    cudaGetSymbolAddress((void**)&xn_, g_xn);
    cudaGetSymbolAddress((void**)&ff1_,g_ff1);

    cudaFuncSetAttribute(attn_mma, cudaFuncAttributeMaxDynamicSharedMemorySize, SMEM_ATTN);
    cudaFuncSetAttribute(gemm_bf16x3<128,128>, cudaFuncAttributeMaxDynamicSharedMemorySize, SMEM_G128);
    cudaFuncSetAttribute(gemm_bf16x3<64,64>,   cudaFuncAttributeMaxDynamicSharedMemorySize, SMEM_G64);

    // LN1 / LN2
    ln_kernel<<<LQ * BB, 256>>>(tgt,    ln1w, ln1b, t_);
    ln_kernel<<<LK * BB, 256>>>(memory, ln2w, ln2b, m_);

    // Q/K/V projections
    gemm_bf16x3<64,64>  <<<dim3(DD / 64,  (LQ * BB) / 64),  256, SMEM_G64 >>>(t_, Wq, bq, nullptr, q_, DD, DD, 0);
    gemm_bf16x3<128,128><<<dim3(DD / 128, (LK * BB) / 128), 256, SMEM_G128>>>(m_, Wk, bk, nullptr, k_, DD, DD, 0);
    gemm_bf16x3<128,128><<<dim3(DD / 128, (LK * BB) / 128), 256, SMEM_G128>>>(m_, Wv, bv, nullptr, v_, DD, DD, 0);

    // MMA banded attention
    attn_mma<<<dim3(LQ / 16, BB), 256, SMEM_ATTN>>>(q_, k_, v_, ctx_, out_aw);

    // output projection + residual, LN3
    gemm_bf16x3<64,64><<<dim3(DD / 64, (LQ * BB) / 64), 256, SMEM_G64>>>(ctx_, Wo, bo, t_, x1_, DD, DD, 0);
    ln_kernel<<<LQ * BB, 256>>>(x1_, ln3w, ln3b, xn_);

    // FFN
    gemm_bf16x3<128,128><<<dim3(DFF / 128, (LQ * BB) / 128), 256, SMEM_G128>>>(xn_, W1, b1, nullptr, ff1_, DFF, DD, 1);
    gemm_bf16x3<64,64>  <<<dim3(DD / 64,   (LQ * BB) / 64),  256, SMEM_G64 >>>(ff1_, W2, b2, xn_, x1_, DD, DFF, 0);

    // LN4 -> output x
    ln_kernel<<<LQ * BB, 256>>>(x1_, ln4w, ln4b, out_x);
}

// round 7
// speedup vs baseline: 2.0779x; 1.0619x over previous
#include <cuda_runtime.h>
#include <cuda_bf16.h>
#include <math.h>
#include <stdint.h>

// Problem constants
#define LQ   512
#define LK   4096
#define BB   4
#define DD   512
#define DFF  2048
#define HH   8
#define HD   64
#define LKH  (LK / 2)
#define LN_EPS 1e-5f

// ------------------------- scratch (device globals) -----------------------
__device__ float  g_t  [LQ * BB * DD];
__device__ float  g_q  [LQ * BB * DD];
__device__ float  g_ctx[LQ * BB * DD];
__device__ float  g_x1 [LQ * BB * DD];
__device__ float  g_xn [LQ * BB * DD];
__device__ float  g_ff1[LQ * BB * DFF];
__device__ float2 g_rs [LK * BB];                     // LN2 row stats (mu, rstd)
__device__ uint32_t g_kh [LK * BB * (DD / 2)];        // K bf16-hi packed along d
__device__ uint32_t g_kl [LK * BB * (DD / 2)];        // K bf16-lo
__device__ uint32_t g_vth[BB * DD * LKH + 64];        // V^T bf16-hi packed along k
__device__ uint32_t g_vtl[BB * DD * LKH + 64];        // V^T bf16-lo

// ------------------------- reductions ------------------------------------
__device__ __forceinline__ float warpReduceSum(float v) {
    #pragma unroll
    for (int o = 16; o > 0; o >>= 1) v += __shfl_down_sync(0xffffffffu, v, o);
    return v;
}
__device__ __forceinline__ float blockReduceSum256(float v, float* shared) {
    __syncthreads();
    int lane = threadIdx.x & 31, wid = threadIdx.x >> 5;
    v = warpReduceSum(v);
    if (lane == 0) shared[wid] = v;
    __syncthreads();
    if (wid == 0) {
        float x = (lane < 8) ? shared[lane] : 0.f;
        #pragma unroll
        for (int o = 4; o > 0; o >>= 1) x += __shfl_down_sync(0xffffffffu, x, o);
        if (lane == 0) shared[0] = x;
    }
    __syncthreads();
    return shared[0];
}

// ------------------------- LayerNorm (row length 512) ---------------------
__global__ void ln_kernel(const float* __restrict__ in,
                          const float* __restrict__ w,
                          const float* __restrict__ b,
                          float* __restrict__ out)
{
    __shared__ float red[8];
    const int r = blockIdx.x;
    const float* xp = in + (size_t)r * DD;
    float* op = out + (size_t)r * DD;
    int t = threadIdx.x;

    float x0 = xp[t], x1 = xp[t + 256];
    float s = blockReduceSum256(x0 + x1, red);
    float mu = s * (1.0f / DD);
    float d0 = x0 - mu, d1 = x1 - mu;
    float ss = blockReduceSum256(d0 * d0 + d1 * d1, red);
    float rstd = rsqrtf(ss * (1.0f / DD) + LN_EPS);
    op[t]       = d0 * rstd * w[t]       + b[t];
    op[t + 256] = d1 * rstd * w[t + 256] + b[t + 256];
}

// ------------------------- row statistics for fused LN2 --------------------
__global__ void rowstat_kernel(const float* __restrict__ in, float2* __restrict__ rs)
{
    const int row  = blockIdx.x * 8 + (threadIdx.x >> 5);
    const int lane = threadIdx.x & 31;
    const float4* p = (const float4*)(in + (size_t)row * DD);
    float s = 0.f, s2 = 0.f;
    #pragma unroll
    for (int i = 0; i < 4; i++) {
        float4 v = p[lane + 32 * i];
        s  += v.x + v.y + v.z + v.w;
        s2 += v.x * v.x + v.y * v.y + v.z * v.z + v.w * v.w;
    }
    s  = warpReduceSum(s);
    s2 = warpReduceSum(s2);
    if (lane == 0) {
        float mu  = s * (1.0f / DD);
        float var = s2 * (1.0f / DD) - mu * mu;
        rs[row] = make_float2(mu, rsqrtf(var + LN_EPS));
    }
}

// ------------------------- bf16 helpers ------------------------------------
__device__ __forceinline__ uint32_t pk(__nv_bfloat16 lo, __nv_bfloat16 hi) {
    unsigned short a = __bfloat16_as_ushort(lo);
    unsigned short b = __bfloat16_as_ushort(hi);
    return (uint32_t)a | ((uint32_t)b << 16);
}
__device__ __forceinline__ void split2(float2 f, uint32_t& h, uint32_t& l) {
    __nv_bfloat16 h0 = __float2bfloat16(f.x), h1 = __float2bfloat16(f.y);
    __nv_bfloat16 l0 = __float2bfloat16(f.x - __bfloat162float(h0));
    __nv_bfloat16 l1 = __float2bfloat16(f.y - __bfloat162float(h1));
    h = pk(h0, h1); l = pk(l0, l1);
}
__device__ __forceinline__ void mma_bf16(float* d, const uint32_t* a, const uint32_t* b) {
    asm volatile(
        "mma.sync.aligned.m16n8k16.row.col.f32.bf16.bf16.f32 "
        "{%0,%1,%2,%3}, {%4,%5,%6,%7}, {%8,%9}, {%0,%1,%2,%3};"
        : "+f"(d[0]), "+f"(d[1]), "+f"(d[2]), "+f"(d[3])
        : "r"(a[0]), "r"(a[1]), "r"(a[2]), "r"(a[3]), "r"(b[0]), "r"(b[1]));
}

// ------------------------- GEMM: out[R,N] = A[R,K] @ W[N,K]^T + bias ------
// MODE 0: float out (+relu/res). MODE 1: packed bf16 hi/lo out (K layout).
// MODE 2: transposed packed bf16 hi/lo out (V^T layout, via smem restage).
// LNF: apply layernorm (rowstat + lnw/lnb) to A during staging.
#define SKS 12

template<int BM, int BN, int MODE, int LNF>
__global__ __launch_bounds__(256) void gemm_bf16x3(
        const float* __restrict__ A,
        const float* __restrict__ W,
        const float* __restrict__ bias,
        const float* __restrict__ res,
        float* __restrict__ out,
        uint32_t* __restrict__ oh,
        uint32_t* __restrict__ ol,
        const float2* __restrict__ rowstat,
        const float* __restrict__ lnw,
        const float* __restrict__ lnb,
        int N, int K, int doRelu)
{
    constexpr int FM = BM / 32;
    constexpr int FN = BN / 32;
    constexpr int LA = BM / 64;
    constexpr int LB = BN / 64;

    extern __shared__ uint32_t usmem[];
    uint32_t* sAh = usmem;
    uint32_t* sAl = sAh + 2 * BM * SKS;
    uint32_t* sBh = sAl + 2 * BM * SKS;
    uint32_t* sBl = sBh + 2 * BN * SKS;

    const int tid  = threadIdx.x;
    const int lane = tid & 31;
    const int warp = tid >> 5;
    const int g = lane >> 2, t = lane & 3;
    const int mW = (warp & 1) * (BM / 2);
    const int nW = (warp >> 1) * (BN / 4);
    const int rowBase = blockIdx.y * BM;
    const int colBase = blockIdx.x * BN;

    const int lr = tid >> 2;
    const int lc = (tid & 3) * 4;
    const float* Ag = A + (size_t)(rowBase + lr) * K + lc;
    const float* Wg = W + (size_t)(colBase + lr) * K + lc;

    float2 rs[2];
    if (LNF) {
        rs[0] = rowstat[rowBase + lr];
        if (LA > 1) rs[1] = rowstat[rowBase + lr + 64];
    }

    float acc[FM][FN][4];
    #pragma unroll
    for (int i = 0; i < FM; i++)
        #pragma unroll
        for (int j = 0; j < FN; j++)
            #pragma unroll
            for (int c = 0; c < 4; c++) acc[i][j][c] = 0.f;

    float4 ra[LA], rw[LB];

    auto loadTile = [&](int tt) {
        #pragma unroll
        for (int i = 0; i < LA; i++) ra[i] = *(const float4*)(Ag + (size_t)i * 64 * K + tt * 16);
        #pragma unroll
        for (int i = 0; i < LB; i++) rw[i] = *(const float4*)(Wg + (size_t)i * 64 * K + tt * 16);
        if (LNF) {
            float4 lw = *(const float4*)(lnw + tt * 16 + lc);
            float4 lb = *(const float4*)(lnb + tt * 16 + lc);
            #pragma unroll
            for (int i = 0; i < LA; i++) {
                float mu = rs[i].x, rd = rs[i].y;
                ra[i].x = (ra[i].x - mu) * rd * lw.x + lb.x;
                ra[i].y = (ra[i].y - mu) * rd * lw.y + lb.y;
                ra[i].z = (ra[i].z - mu) * rd * lw.z + lb.z;
                ra[i].w = (ra[i].w - mu) * rd * lw.w + lb.w;
            }
        }
    };

    auto stage = [&](int buf) {
        #pragma unroll
        for (int i = 0; i < LA; i++) {
            float4 v = ra[i];
            uint32_t h0, l0, h1, l1;
            split2(make_float2(v.x, v.y), h0, l0);
            split2(make_float2(v.z, v.w), h1, l1);
            int ofs = buf * BM * SKS + (lr + 64 * i) * SKS + (lc >> 1);
            *(uint2*)(sAh + ofs) = make_uint2(h0, h1);
            *(uint2*)(sAl + ofs) = make_uint2(l0, l1);
        }
        #pragma unroll
        for (int i = 0; i < LB; i++) {
            float4 v = rw[i];
            uint32_t h0, l0, h1, l1;
            split2(make_float2(v.x, v.y), h0, l0);
            split2(make_float2(v.z, v.w), h1, l1);
            int ofs = buf * BN * SKS + (lr + 64 * i) * SKS + (lc >> 1);
            *(uint2*)(sBh + ofs) = make_uint2(h0, h1);
            *(uint2*)(sBl + ofs) = make_uint2(l0, l1);
        }
    };

    auto compute = [&](int buf) {
        const uint32_t* pAh = sAh + buf * BM * SKS;
        const uint32_t* pAl = sAl + buf * BM * SKS;
        const uint32_t* pBh = sBh + buf * BN * SKS;
        const uint32_t* pBl = sBl + buf * BN * SKS;
        uint32_t ah[FM][4], al[FM][4], bh[FN][2], bl[FN][2];
        #pragma unroll
        for (int mf = 0; mf < FM; mf++) {
            int r0 = mW + mf * 16 + g;
            ah[mf][0] = pAh[r0 * SKS + t];
            ah[mf][1] = pAh[(r0 + 8) * SKS + t];
            ah[mf][2] = pAh[r0 * SKS + t + 4];
            ah[mf][3] = pAh[(r0 + 8) * SKS + t + 4];
            al[mf][0] = pAl[r0 * SKS + t];
            al[mf][1] = pAl[(r0 + 8) * SKS + t];
            al[mf][2] = pAl[r0 * SKS + t + 4];
            al[mf][3] = pAl[(r0 + 8) * SKS + t + 4];
        }
        #pragma unroll
        for (int nf = 0; nf < FN; nf++) {
            int c0 = nW + nf * 8 + g;
            bh[nf][0] = pBh[c0 * SKS + t];
            bh[nf][1] = pBh[c0 * SKS + t + 4];
            bl[nf][0] = pBl[c0 * SKS + t];
            bl[nf][1] = pBl[c0 * SKS + t + 4];
        }
        #pragma unroll
        for (int mf = 0; mf < FM; mf++)
            #pragma unroll
            for (int nf = 0; nf < FN; nf++) {
                mma_bf16(acc[mf][nf], ah[mf], bh[nf]);
                mma_bf16(acc[mf][nf], ah[mf], bl[nf]);
                mma_bf16(acc[mf][nf], al[mf], bh[nf]);
            }
    };

    loadTile(0);
    stage(0);
    __syncthreads();

    const int nT = K / 16;
    int buf = 0;
    for (int tt = 1; tt < nT; tt++) {
        loadTile(tt);
        compute(buf);
        stage(buf ^ 1);
        __syncthreads();
        buf ^= 1;
    }
    compute(buf);

    if (MODE == 0) {
        #pragma unroll
        for (int mf = 0; mf < FM; mf++) {
            int row0 = rowBase + mW + mf * 16 + g;
            #pragma unroll
            for (int nf = 0; nf < FN; nf++) {
                int col = colBase + nW + nf * 8 + 2 * t;
                float2 bb = *(const float2*)(bias + col);
                float2 v0, v1;
                v0.x = acc[mf][nf][0] + bb.x; v0.y = acc[mf][nf][1] + bb.y;
                v1.x = acc[mf][nf][2] + bb.x; v1.y = acc[mf][nf][3] + bb.y;
                if (doRelu) {
                    v0.x = fmaxf(v0.x, 0.f); v0.y = fmaxf(v0.y, 0.f);
                    v1.x = fmaxf(v1.x, 0.f); v1.y = fmaxf(v1.y, 0.f);
                }
                if (res) {
                    float2 r0 = *(const float2*)(res + (size_t)row0 * N + col);
                    float2 r1 = *(const float2*)(res + (size_t)(row0 + 8) * N + col);
                    v0.x += r0.x; v0.y += r0.y;
                    v1.x += r1.x; v1.y += r1.y;
                }
                *(float2*)(out + (size_t)row0 * N + col) = v0;
                *(float2*)(out + (size_t)(row0 + 8) * N + col) = v1;
            }
        }
    } else if (MODE == 1) {
        // packed bf16 hi/lo along columns (d): oh[row][col/2]
        #pragma unroll
        for (int mf = 0; mf < FM; mf++) {
            int row0 = rowBase + mW + mf * 16 + g;
            #pragma unroll
            for (int nf = 0; nf < FN; nf++) {
                int col = colBase + nW + nf * 8 + 2 * t;
                float2 bb = *(const float2*)(bias + col);
                uint32_t h0, l0, h1, l1;
                split2(make_float2(acc[mf][nf][0] + bb.x, acc[mf][nf][1] + bb.y), h0, l0);
                split2(make_float2(acc[mf][nf][2] + bb.x, acc[mf][nf][3] + bb.y), h1, l1);
                size_t i0 = (size_t)row0 * (N >> 1) + (col >> 1);
                size_t i1 = (size_t)(row0 + 8) * (N >> 1) + (col >> 1);
                oh[i0] = h0; ol[i0] = l0;
                oh[i1] = h1; ol[i1] = l1;
            }
        }
    } else {
        // MODE 2: transposed V^T output via smem restage. Rows are (k*BB+b).
        float* smf = (float*)usmem;     // [BM][68]
        #pragma unroll
        for (int p = 0; p < BN / 64; p++) {
            __syncthreads();
            #pragma unroll
            for (int mf = 0; mf < FM; mf++) {
                int r0 = mW + mf * 16 + g;
                #pragma unroll
                for (int nf = 0; nf < FN; nf++) {
                    int col = nW + nf * 8 + 2 * t;
                    if ((col >> 6) == p) {
                        int ch = col & 63;
                        float2 bb = *(const float2*)(bias + colBase + col);
                        smf[r0 * 68 + ch]           = acc[mf][nf][0] + bb.x;
                        smf[r0 * 68 + ch + 1]       = acc[mf][nf][1] + bb.y;
                        smf[(r0 + 8) * 68 + ch]     = acc[mf][nf][2] + bb.x;
                        smf[(r0 + 8) * 68 + ch + 1] = acc[mf][nf][3] + bb.y;
                    }
                }
            }
            __syncthreads();
            // read transposed: thread -> (b, d); pairs along k
            const int bq = tid & 3;
            const int d  = tid >> 2;          // 0..63
            const int dg = colBase + p * 64 + d;
            uint32_t hbuf[16], lbuf[16];
            #pragma unroll
            for (int j = 0; j < 16; j++) {
                float v0 = smf[(8 * j + bq) * 68 + d];
                float v1 = smf[(8 * j + 4 + bq) * 68 + d];
                split2(make_float2(v0, v1), hbuf[j], lbuf[j]);
            }
            size_t base = ((size_t)bq * DD + dg) * LKH + (rowBase >> 3);
            #pragma unroll
            for (int i = 0; i < 4; i++) {
                *(uint4*)(oh + base + 4 * i) = make_uint4(hbuf[4*i], hbuf[4*i+1], hbuf[4*i+2], hbuf[4*i+3]);
                *(uint4*)(ol + base + 4 * i) = make_uint4(lbuf[4*i], lbuf[4*i+1], lbuf[4*i+2], lbuf[4*i+3]);
            }
        }
    }
}

#define SMEM_G128 (16 * SKS * (128 + 128))
#define SMEM_G64  (16 * SKS * (64 + 64))

// ------------------------- MMA banded attention ----------------------------
// 16 q-rows per block, grid (32, 4). K/V pre-split bf16 hi/lo in global.
#define SQS 260          // Q smem stride (u32 pairs)
#define SSW 968          // S / awsum stride (f32)
#define SMEM_ATTN ((2 * 16 * SQS + 2 * 16 * SSW + 16) * 4)

__device__ __forceinline__ int band_start(int qi) { return (qi >= 409) ? 3268 : qi * 8; }
__device__ __forceinline__ int band_wd(int qi)    { return (qi >= 409) ? 828  : 827; }

__global__ __launch_bounds__(256) void attn_mma(
        const float* __restrict__ q,
        const uint32_t* __restrict__ kh,
        const uint32_t* __restrict__ kl,
        const uint32_t* __restrict__ vth,
        const uint32_t* __restrict__ vtl,
        float* __restrict__ ctx,
        float* __restrict__ aw)
{
    extern __shared__ uint32_t sm[];
    uint32_t* sQh = sm;                         // [16][SQS]
    uint32_t* sQl = sQh + 16 * SQS;
    float*    sS  = (float*)(sQl + 16 * SQS);   // [16][SSW]
    float*    aws = sS + 16 * SSW;              // [16][SSW]
    float*    sInvH = aws + 16 * SSW;           // [16]

    const int qi0 = blockIdx.x * 16;
    const int b   = blockIdx.y;
    const int tid = threadIdx.x;
    const int lane = tid & 31;
    const int warp = tid >> 5;
    const int g = lane >> 2, t = lane & 3;

    const int ustart = band_start(qi0);
    const int uend   = band_start(qi0 + 15) + band_wd(qi0 + 15);
    const int uW     = uend - ustart;
    const int ngroups = (uW + 7) >> 3;
    const int KPAD    = ((uW + 15) >> 4) << 4;

    // stage Q (scaled by 1/8) as bf16 hi/lo pairs
    for (int i = tid; i < 16 * 256; i += 256) {
        int r = i >> 8, c = i & 255;
        float2 f = *(const float2*)(q + ((size_t)(qi0 + r) * BB + b) * DD + 2 * c);
        f.x *= 0.125f; f.y *= 0.125f;
        uint32_t h, l;
        split2(f, h, l);
        sQh[r * SQS + c] = h;
        sQl[r * SQS + c] = l;
    }

    for (int h = 0; h < HH; h++) {
        __syncthreads();

        // hoist Q a-frags for this head
        uint32_t qah[4][4], qal[4][4];
        #pragma unroll
        for (int ks = 0; ks < 4; ks++) {
            int base = g * SQS + h * 32 + ks * 8 + t;
            qah[ks][0] = sQh[base];
            qah[ks][1] = sQh[base + 8 * SQS];
            qah[ks][2] = sQh[base + 4];
            qah[ks][3] = sQh[base + 8 * SQS + 4];
            qal[ks][0] = sQl[base];
            qal[ks][1] = sQl[base + 8 * SQS];
            qal[ks][2] = sQl[base + 4];
            qal[ks][3] = sQl[base + 8 * SQS + 4];
        }

        // ---- scores: pre-split K fragments straight from global ----
        for (int grp = warp; grp < ngroups; grp += 8) {
            int key = ustart + grp * 8 + g;
            if (key > LK - 1) key = LK - 1;
            const uint32_t* krh = kh + ((size_t)key * BB + b) * (DD / 2) + h * 32;
            const uint32_t* krl = kl + ((size_t)key * BB + b) * (DD / 2) + h * 32;
            float acc[4] = {0.f, 0.f, 0.f, 0.f};
            #pragma unroll
            for (int ks = 0; ks < 4; ks++) {
                uint32_t bh[2], bl[2];
                bh[0] = krh[ks * 8 + t];
                bh[1] = krh[ks * 8 + t + 4];
                bl[0] = krl[ks * 8 + t];
                bl[1] = krl[ks * 8 + t + 4];
                mma_bf16(acc, qah[ks], bh);
                mma_bf16(acc, qah[ks], bl);
                mma_bf16(acc, qal[ks], bh);
            }
            *(float2*)(sS + g * SSW + grp * 8 + 2 * t)       = make_float2(acc[0], acc[1]);
            *(float2*)(sS + (g + 8) * SSW + grp * 8 + 2 * t) = make_float2(acc[2], acc[3]);
        }
        __syncthreads();

        // ---- softmax + head-mean accumulation + zero padding ----
        #pragma unroll
        for (int rr = 0; rr < 2; rr++) {
            const int r  = warp + rr * 8;
            const int qi = qi0 + r;
            const int j0 = band_start(qi) - ustart;
            const int W  = band_wd(qi);
            float* srow = sS + r * SSW;

            float m = -1e30f;
            for (int i = j0 + lane; i < j0 + W; i += 32) m = fmaxf(m, srow[i]);
            #pragma unroll
            for (int o = 16; o > 0; o >>= 1) m = fmaxf(m, __shfl_xor_sync(0xffffffffu, m, o));
            float sum = 0.f;
            for (int i = j0 + lane; i < j0 + W; i += 32) {
                float e = __expf(srow[i] - m);
                srow[i] = e;
                sum += e;
            }
            #pragma unroll
            for (int o = 16; o > 0; o >>= 1) sum += __shfl_xor_sync(0xffffffffu, sum, o);
            float inv = 1.0f / sum;
            if (lane == 0) sInvH[r] = inv;

            float cc = inv * 0.125f;   // 1/H
            float* arow = aws + r * SSW;
            if (h == 0) {
                for (int i = j0 + lane; i < j0 + W; i += 32) arow[i] = srow[i] * cc;
            } else {
                for (int i = j0 + lane; i < j0 + W; i += 32) arow[i] += srow[i] * cc;
            }
            for (int i = lane; i < j0; i += 32) srow[i] = 0.f;
            for (int i = j0 + W + lane; i < KPAD; i += 32) srow[i] = 0.f;
        }
        __syncthreads();

        // ---- context: pre-split V^T fragments straight from global ----
        {
            const int dimBase = h * 64 + warp * 8;
            float cacc[4] = {0.f, 0.f, 0.f, 0.f};
            const int nchunks = KPAD >> 4;
            const uint32_t* vhc = vth + ((size_t)b * DD + dimBase + g) * LKH;
            const uint32_t* vlc = vtl + ((size_t)b * DD + dimBase + g) * LKH;
            const int kbase = ustart >> 1;
            for (int ck = 0; ck < nchunks; ck++) {
                const float* pr0 = sS + g * SSW + ck * 16 + 2 * t;
                const float* pr8 = sS + (g + 8) * SSW + ck * 16 + 2 * t;
                float2 p0 = *(const float2*)(pr0);
                float2 p2 = *(const float2*)(pr8);
                float2 p1 = *(const float2*)(pr0 + 8);
                float2 p3 = *(const float2*)(pr8 + 8);
                uint32_t ah[4], al[4];
                split2(p0, ah[0], al[0]);
                split2(p2, ah[1], al[1]);
                split2(p1, ah[2], al[2]);
                split2(p3, ah[3], al[3]);

                int kp2 = kbase + ck * 8 + t;
                uint32_t bh[2], bl[2];
                bh[0] = vhc[kp2];
                bh[1] = vhc[kp2 + 4];
                bl[0] = vlc[kp2];
                bl[1] = vlc[kp2 + 4];

                mma_bf16(cacc, ah, bh);
                mma_bf16(cacc, ah, bl);
                mma_bf16(cacc, al, bh);
            }
            float inv0 = sInvH[g];
            float inv1 = sInvH[g + 8];
            *(float2*)(ctx + ((size_t)(qi0 + g) * BB + b) * DD + dimBase + 2 * t) =
                make_float2(cacc[0] * inv0, cacc[1] * inv0);
            *(float2*)(ctx + ((size_t)(qi0 + g + 8) * BB + b) * DD + dimBase + 2 * t) =
                make_float2(cacc[2] * inv1, cacc[3] * inv1);
        }
    }
    __syncthreads();

    // ---- final attn_weights write (zeros outside band) ----
    for (int i = tid; i < 16 * 1024; i += 256) {
        int r  = i >> 10;
        int c  = (i & 1023) << 2;
        int qi = qi0 + r;
        int s0 = band_start(qi);
        int W  = band_wd(qi);
        const float* arow = aws + r * SSW;
        float4 o;
        {
            int j = c + 0, jj = j - s0;
            o.x = (jj >= 0 && jj < W) ? arow[j - ustart] : 0.f;
            j = c + 1; jj = j - s0;
            o.y = (jj >= 0 && jj < W) ? arow[j - ustart] : 0.f;
            j = c + 2; jj = j - s0;
            o.z = (jj >= 0 && jj < W) ? arow[j - ustart] : 0.f;
            j = c + 3; jj = j - s0;
            o.w = (jj >= 0 && jj < W) ? arow[j - ustart] : 0.f;
        }
        *(float4*)(aw + ((size_t)b * LQ + qi) * LK + c) = o;
    }
}

// ------------------------- launch -----------------------------------------
extern "C" void kernel_launch(void* const* d_in, const int* in_sizes, int n_in,
                              void* d_out, int out_size)
{
    const float* tgt    = (const float*)d_in[0];
    const float* memory = (const float*)d_in[1];
    const float* Wq = (const float*)d_in[2];  const float* bq = (const float*)d_in[3];
    const float* Wk = (const float*)d_in[4];  const float* bk = (const float*)d_in[5];
    const float* Wv = (const float*)d_in[6];  const float* bv = (const float*)d_in[7];
    const float* Wo = (const float*)d_in[8];  const float* bo = (const float*)d_in[9];
    const float* W1 = (const float*)d_in[10]; const float* b1 = (const float*)d_in[11];
    const float* W2 = (const float*)d_in[12]; const float* b2 = (const float*)d_in[13];
    const float* ln1w = (const float*)d_in[14]; const float* ln1b = (const float*)d_in[15];
    const float* ln2w = (const float*)d_in[16]; const float* ln2b = (const float*)d_in[17];
    const float* ln3w = (const float*)d_in[18]; const float* ln3b = (const float*)d_in[19];
    const float* ln4w = (const float*)d_in[20]; const float* ln4b = (const float*)d_in[21];

    float* out    = (float*)d_out;
    float* out_x  = out;
    float* out_aw = out + (size_t)LQ * BB * DD;

    float *t_, *q_, *ctx_, *x1_, *xn_, *ff1_;
    float2* rs_;
    uint32_t *kh_, *kl_, *vth_, *vtl_;
    cudaGetSymbolAddress((void**)&t_,   g_t);
    cudaGetSymbolAddress((void**)&q_,   g_q);
    cudaGetSymbolAddress((void**)&ctx_, g_ctx);
    cudaGetSymbolAddress((void**)&x1_,  g_x1);
    cudaGetSymbolAddress((void**)&xn_,  g_xn);
    cudaGetSymbolAddress((void**)&ff1_, g_ff1);
    cudaGetSymbolAddress((void**)&rs_,  g_rs);
    cudaGetSymbolAddress((void**)&kh_,  g_kh);
    cudaGetSymbolAddress((void**)&kl_,  g_kl);
    cudaGetSymbolAddress((void**)&vth_, g_vth);
    cudaGetSymbolAddress((void**)&vtl_, g_vtl);

    cudaFuncSetAttribute(attn_mma, cudaFuncAttributeMaxDynamicSharedMemorySize, SMEM_ATTN);
    cudaFuncSetAttribute(gemm_bf16x3<128,128,0,0>, cudaFuncAttributeMaxDynamicSharedMemorySize, SMEM_G128);
    cudaFuncSetAttribute(gemm_bf16x3<128,128,1,1>, cudaFuncAttributeMaxDynamicSharedMemorySize, SMEM_G128);
    cudaFuncSetAttribute(gemm_bf16x3<128,128,2,1>, cudaFuncAttributeMaxDynamicSharedMemorySize, SMEM_G128);
    cudaFuncSetAttribute(gemm_bf16x3<64,64,0,0>,   cudaFuncAttributeMaxDynamicSharedMemorySize, SMEM_G64);

    // LN1 (materialized; needed as residual) + LN2 row stats
    ln_kernel<<<LQ * BB, 256>>>(tgt, ln1w, ln1b, t_);
    rowstat_kernel<<<(LK * BB) / 8, 256>>>(memory, rs_);

    // Q projection (float out)
    gemm_bf16x3<64,64,0,0><<<dim3(DD / 64, (LQ * BB) / 64), 256, SMEM_G64>>>(
        t_, Wq, bq, nullptr, q_, nullptr, nullptr, nullptr, nullptr, nullptr, DD, DD, 0);

    // K projection: fused LN2, packed bf16 hi/lo out
    gemm_bf16x3<128,128,1,1><<<dim3(DD / 128, (LK * BB) / 128), 256, SMEM_G128>>>(
        memory, Wk, bk, nullptr, nullptr, kh_, kl_, rs_, ln2w, ln2b, DD, DD, 0);

    // V projection: fused LN2, transposed packed bf16 hi/lo out
    gemm_bf16x3<128,128,2,1><<<dim3(DD / 128, (LK * BB) / 128), 256, SMEM_G128>>>(
        memory, Wv, bv, nullptr, nullptr, vth_, vtl_, rs_, ln2w, ln2b, DD, DD, 0);

    // MMA banded attention
    attn_mma<<<dim3(LQ / 16, BB), 256, SMEM_ATTN>>>(q_, kh_, kl_, vth_, vtl_, ctx_, out_aw);

    // output projection + residual, LN3
    gemm_bf16x3<64,64,0,0><<<dim3(DD / 64, (LQ * BB) / 64), 256, SMEM_G64>>>(
        ctx_, Wo, bo, t_, x1_, nullptr, nullptr, nullptr, nullptr, nullptr, DD, DD, 0);
    ln_kernel<<<LQ * BB, 256>>>(x1_, ln3w, ln3b, xn_);

    // FFN
    gemm_bf16x3<128,128,0,0><<<dim3(DFF / 128, (LQ * BB) / 128), 256, SMEM_G128>>>(
        xn_, W1, b1, nullptr, ff1_, nullptr, nullptr, nullptr, nullptr, nullptr, DFF, DD, 1);
    gemm_bf16x3<64,64,0,0><<<dim3(DD / 64, (LQ * BB) / 64), 256, SMEM_G64>>>(
        ff1_, W2, b2, xn_, x1_, nullptr, nullptr, nullptr, nullptr, nullptr, DD, DFF, 0);

    // LN4 -> output x
    ln_kernel<<<LQ * BB, 256>>>(x1_, ln4w, ln4b, out_x);
}

// round 8
// speedup vs baseline: 2.2624x; 1.0888x over previous
#include <cuda_runtime.h>
#include <cuda_bf16.h>
#include <math.h>
#include <stdint.h>

// Problem constants
#define LQ   512
#define LK   4096
#define BB   4
#define DD   512
#define DFF  2048
#define HH   8
#define HD   64
#define LKH  (LK / 2)
#define LN_EPS 1e-5f

// ------------------------- scratch (device globals) -----------------------
__device__ float  g_t  [LQ * BB * DD];
__device__ float  g_q  [LQ * BB * DD];
__device__ float  g_ctx[LQ * BB * DD];
__device__ float  g_x1 [LQ * BB * DD];
__device__ float  g_xn [LQ * BB * DD];
__device__ float  g_ff1[LQ * BB * DFF];
__device__ float2 g_rs [LK * BB];                     // LN2 row stats (mu, rstd)
__device__ uint32_t g_kh [LK * BB * (DD / 2)];        // K bf16-hi packed along d
__device__ uint32_t g_kl [LK * BB * (DD / 2)];        // K bf16-lo
__device__ uint32_t g_vth[BB * DD * LKH + 64];        // V^T bf16-hi packed along k
__device__ uint32_t g_vtl[BB * DD * LKH + 64];        // V^T bf16-lo

// ------------------------- reductions ------------------------------------
__device__ __forceinline__ float warpReduceSum(float v) {
    #pragma unroll
    for (int o = 16; o > 0; o >>= 1) v += __shfl_down_sync(0xffffffffu, v, o);
    return v;
}
__device__ __forceinline__ float blockReduceSum256(float v, float* shared) {
    __syncthreads();
    int lane = threadIdx.x & 31, wid = threadIdx.x >> 5;
    v = warpReduceSum(v);
    if (lane == 0) shared[wid] = v;
    __syncthreads();
    if (wid == 0) {
        float x = (lane < 8) ? shared[lane] : 0.f;
        #pragma unroll
        for (int o = 4; o > 0; o >>= 1) x += __shfl_down_sync(0xffffffffu, x, o);
        if (lane == 0) shared[0] = x;
    }
    __syncthreads();
    return shared[0];
}

// ------------------------- LayerNorm (row length 512) ---------------------
__global__ void ln_kernel(const float* __restrict__ in,
                          const float* __restrict__ w,
                          const float* __restrict__ b,
                          float* __restrict__ out)
{
    __shared__ float red[8];
    const int r = blockIdx.x;
    const float* xp = in + (size_t)r * DD;
    float* op = out + (size_t)r * DD;
    int t = threadIdx.x;

    float x0 = xp[t], x1 = xp[t + 256];
    float s = blockReduceSum256(x0 + x1, red);
    float mu = s * (1.0f / DD);
    float d0 = x0 - mu, d1 = x1 - mu;
    float ss = blockReduceSum256(d0 * d0 + d1 * d1, red);
    float rstd = rsqrtf(ss * (1.0f / DD) + LN_EPS);
    op[t]       = d0 * rstd * w[t]       + b[t];
    op[t + 256] = d1 * rstd * w[t + 256] + b[t + 256];
}

// ------------------------- row statistics for fused LN2 --------------------
__global__ void rowstat_kernel(const float* __restrict__ in, float2* __restrict__ rs)
{
    const int row  = blockIdx.x * 8 + (threadIdx.x >> 5);
    const int lane = threadIdx.x & 31;
    const float4* p = (const float4*)(in + (size_t)row * DD);
    float s = 0.f, s2 = 0.f;
    #pragma unroll
    for (int i = 0; i < 4; i++) {
        float4 v = p[lane + 32 * i];
        s  += v.x + v.y + v.z + v.w;
        s2 += v.x * v.x + v.y * v.y + v.z * v.z + v.w * v.w;
    }
    s  = warpReduceSum(s);
    s2 = warpReduceSum(s2);
    if (lane == 0) {
        float mu  = s * (1.0f / DD);
        float var = s2 * (1.0f / DD) - mu * mu;
        rs[row] = make_float2(mu, rsqrtf(var + LN_EPS));
    }
}

// ------------------------- bf16 helpers ------------------------------------
__device__ __forceinline__ uint32_t pk(__nv_bfloat16 lo, __nv_bfloat16 hi) {
    unsigned short a = __bfloat16_as_ushort(lo);
    unsigned short b = __bfloat16_as_ushort(hi);
    return (uint32_t)a | ((uint32_t)b << 16);
}
__device__ __forceinline__ void split2(float2 f, uint32_t& h, uint32_t& l) {
    __nv_bfloat16 h0 = __float2bfloat16(f.x), h1 = __float2bfloat16(f.y);
    __nv_bfloat16 l0 = __float2bfloat16(f.x - __bfloat162float(h0));
    __nv_bfloat16 l1 = __float2bfloat16(f.y - __bfloat162float(h1));
    h = pk(h0, h1); l = pk(l0, l1);
}
__device__ __forceinline__ void mma_bf16(float* d, const uint32_t* a, const uint32_t* b) {
    asm volatile(
        "mma.sync.aligned.m16n8k16.row.col.f32.bf16.bf16.f32 "
        "{%0,%1,%2,%3}, {%4,%5,%6,%7}, {%8,%9}, {%0,%1,%2,%3};"
        : "+f"(d[0]), "+f"(d[1]), "+f"(d[2]), "+f"(d[3])
        : "r"(a[0]), "r"(a[1]), "r"(a[2]), "r"(a[3]), "r"(b[0]), "r"(b[1]));
}

// ------------------------- GEMM: out[R,N] = A[R,K] @ W[N,K]^T + bias ------
// MODE 0: float out (+relu/res). MODE 1: packed bf16 hi/lo out (K layout).
// MODE 2: transposed packed bf16 hi/lo out (V^T layout, via smem restage).
// LNF: apply layernorm (rowstat + lnw/lnb) to A during staging.
#define SKS 12

template<int BM, int BN, int MODE, int LNF>
__global__ __launch_bounds__(256, 2) void gemm_bf16x3(
        const float* __restrict__ A,
        const float* __restrict__ W,
        const float* __restrict__ bias,
        const float* __restrict__ res,
        float* __restrict__ out,
        uint32_t* __restrict__ oh,
        uint32_t* __restrict__ ol,
        const float2* __restrict__ rowstat,
        const float* __restrict__ lnw,
        const float* __restrict__ lnb,
        int N, int K, int doRelu)
{
    constexpr int FM = BM / 32;
    constexpr int FN = BN / 32;
    constexpr int LA = BM / 64;
    constexpr int LB = BN / 64;

    extern __shared__ uint32_t usmem[];
    uint32_t* sAh = usmem;
    uint32_t* sAl = sAh + 2 * BM * SKS;
    uint32_t* sBh = sAl + 2 * BM * SKS;
    uint32_t* sBl = sBh + 2 * BN * SKS;

    const int tid  = threadIdx.x;
    const int lane = tid & 31;
    const int warp = tid >> 5;
    const int g = lane >> 2, t = lane & 3;
    const int mW = (warp & 1) * (BM / 2);
    const int nW = (warp >> 1) * (BN / 4);
    const int rowBase = blockIdx.y * BM;
    const int colBase = blockIdx.x * BN;

    const int lr = tid >> 2;
    const int lc = (tid & 3) * 4;
    const float* Ag = A + (size_t)(rowBase + lr) * K + lc;
    const float* Wg = W + (size_t)(colBase + lr) * K + lc;

    float2 rs[2];
    if (LNF) {
        rs[0] = rowstat[rowBase + lr];
        if (LA > 1) rs[1] = rowstat[rowBase + lr + 64];
    }

    float acc[FM][FN][4];
    #pragma unroll
    for (int i = 0; i < FM; i++)
        #pragma unroll
        for (int j = 0; j < FN; j++)
            #pragma unroll
            for (int c = 0; c < 4; c++) acc[i][j][c] = 0.f;

    float4 ra[LA], rw[LB];

    // pure loads only — LN applied later in stage() to shrink live ranges
    auto loadTile = [&](int tt) {
        #pragma unroll
        for (int i = 0; i < LA; i++) ra[i] = *(const float4*)(Ag + (size_t)i * 64 * K + tt * 16);
        #pragma unroll
        for (int i = 0; i < LB; i++) rw[i] = *(const float4*)(Wg + (size_t)i * 64 * K + tt * 16);
    };

    auto stage = [&](int buf, int tt) {
        if (LNF) {
            float4 lw = *(const float4*)(lnw + tt * 16 + lc);
            float4 lb = *(const float4*)(lnb + tt * 16 + lc);
            #pragma unroll
            for (int i = 0; i < LA; i++) {
                float mu = rs[i].x, rd = rs[i].y;
                ra[i].x = (ra[i].x - mu) * rd * lw.x + lb.x;
                ra[i].y = (ra[i].y - mu) * rd * lw.y + lb.y;
                ra[i].z = (ra[i].z - mu) * rd * lw.z + lb.z;
                ra[i].w = (ra[i].w - mu) * rd * lw.w + lb.w;
            }
        }
        #pragma unroll
        for (int i = 0; i < LA; i++) {
            float4 v = ra[i];
            uint32_t h0, l0, h1, l1;
            split2(make_float2(v.x, v.y), h0, l0);
            split2(make_float2(v.z, v.w), h1, l1);
            int ofs = buf * BM * SKS + (lr + 64 * i) * SKS + (lc >> 1);
            *(uint2*)(sAh + ofs) = make_uint2(h0, h1);
            *(uint2*)(sAl + ofs) = make_uint2(l0, l1);
        }
        #pragma unroll
        for (int i = 0; i < LB; i++) {
            float4 v = rw[i];
            uint32_t h0, l0, h1, l1;
            split2(make_float2(v.x, v.y), h0, l0);
            split2(make_float2(v.z, v.w), h1, l1);
            int ofs = buf * BN * SKS + (lr + 64 * i) * SKS + (lc >> 1);
            *(uint2*)(sBh + ofs) = make_uint2(h0, h1);
            *(uint2*)(sBl + ofs) = make_uint2(l0, l1);
        }
    };

    auto compute = [&](int buf) {
        const uint32_t* pAh = sAh + buf * BM * SKS;
        const uint32_t* pAl = sAl + buf * BM * SKS;
        const uint32_t* pBh = sBh + buf * BN * SKS;
        const uint32_t* pBl = sBl + buf * BN * SKS;
        uint32_t ah[FM][4], al[FM][4], bh[FN][2], bl[FN][2];
        #pragma unroll
        for (int mf = 0; mf < FM; mf++) {
            int r0 = mW + mf * 16 + g;
            ah[mf][0] = pAh[r0 * SKS + t];
            ah[mf][1] = pAh[(r0 + 8) * SKS + t];
            ah[mf][2] = pAh[r0 * SKS + t + 4];
            ah[mf][3] = pAh[(r0 + 8) * SKS + t + 4];
            al[mf][0] = pAl[r0 * SKS + t];
            al[mf][1] = pAl[(r0 + 8) * SKS + t];
            al[mf][2] = pAl[r0 * SKS + t + 4];
            al[mf][3] = pAl[(r0 + 8) * SKS + t + 4];
        }
        #pragma unroll
        for (int nf = 0; nf < FN; nf++) {
            int c0 = nW + nf * 8 + g;
            bh[nf][0] = pBh[c0 * SKS + t];
            bh[nf][1] = pBh[c0 * SKS + t + 4];
            bl[nf][0] = pBl[c0 * SKS + t];
            bl[nf][1] = pBl[c0 * SKS + t + 4];
        }
        #pragma unroll
        for (int mf = 0; mf < FM; mf++)
            #pragma unroll
            for (int nf = 0; nf < FN; nf++) {
                mma_bf16(acc[mf][nf], ah[mf], bh[nf]);
                mma_bf16(acc[mf][nf], ah[mf], bl[nf]);
                mma_bf16(acc[mf][nf], al[mf], bh[nf]);
            }
    };

    loadTile(0);
    stage(0, 0);
    __syncthreads();

    const int nT = K / 16;
    int buf = 0;
    for (int tt = 1; tt < nT; tt++) {
        loadTile(tt);
        compute(buf);
        stage(buf ^ 1, tt);
        __syncthreads();
        buf ^= 1;
    }
    compute(buf);

    if (MODE == 0) {
        #pragma unroll
        for (int mf = 0; mf < FM; mf++) {
            int row0 = rowBase + mW + mf * 16 + g;
            #pragma unroll
            for (int nf = 0; nf < FN; nf++) {
                int col = colBase + nW + nf * 8 + 2 * t;
                float2 bb = *(const float2*)(bias + col);
                float2 v0, v1;
                v0.x = acc[mf][nf][0] + bb.x; v0.y = acc[mf][nf][1] + bb.y;
                v1.x = acc[mf][nf][2] + bb.x; v1.y = acc[mf][nf][3] + bb.y;
                if (doRelu) {
                    v0.x = fmaxf(v0.x, 0.f); v0.y = fmaxf(v0.y, 0.f);
                    v1.x = fmaxf(v1.x, 0.f); v1.y = fmaxf(v1.y, 0.f);
                }
                if (res) {
                    float2 r0 = *(const float2*)(res + (size_t)row0 * N + col);
                    float2 r1 = *(const float2*)(res + (size_t)(row0 + 8) * N + col);
                    v0.x += r0.x; v0.y += r0.y;
                    v1.x += r1.x; v1.y += r1.y;
                }
                *(float2*)(out + (size_t)row0 * N + col) = v0;
                *(float2*)(out + (size_t)(row0 + 8) * N + col) = v1;
            }
        }
    } else if (MODE == 1) {
        // packed bf16 hi/lo along columns (d): oh[row][col/2]
        #pragma unroll
        for (int mf = 0; mf < FM; mf++) {
            int row0 = rowBase + mW + mf * 16 + g;
            #pragma unroll
            for (int nf = 0; nf < FN; nf++) {
                int col = colBase + nW + nf * 8 + 2 * t;
                float2 bb = *(const float2*)(bias + col);
                uint32_t h0, l0, h1, l1;
                split2(make_float2(acc[mf][nf][0] + bb.x, acc[mf][nf][1] + bb.y), h0, l0);
                split2(make_float2(acc[mf][nf][2] + bb.x, acc[mf][nf][3] + bb.y), h1, l1);
                size_t i0 = (size_t)row0 * (N >> 1) + (col >> 1);
                size_t i1 = (size_t)(row0 + 8) * (N >> 1) + (col >> 1);
                oh[i0] = h0; ol[i0] = l0;
                oh[i1] = h1; ol[i1] = l1;
            }
        }
    } else {
        // MODE 2: transposed V^T output via smem restage. Rows are (k*BB+b).
        float* smf = (float*)usmem;     // [BM][68]
        #pragma unroll
        for (int p = 0; p < BN / 64; p++) {
            __syncthreads();
            #pragma unroll
            for (int mf = 0; mf < FM; mf++) {
                int r0 = mW + mf * 16 + g;
                #pragma unroll
                for (int nf = 0; nf < FN; nf++) {
                    int col = nW + nf * 8 + 2 * t;
                    if ((col >> 6) == p) {
                        int ch = col & 63;
                        float2 bb = *(const float2*)(bias + colBase + col);
                        smf[r0 * 68 + ch]           = acc[mf][nf][0] + bb.x;
                        smf[r0 * 68 + ch + 1]       = acc[mf][nf][1] + bb.y;
                        smf[(r0 + 8) * 68 + ch]     = acc[mf][nf][2] + bb.x;
                        smf[(r0 + 8) * 68 + ch + 1] = acc[mf][nf][3] + bb.y;
                    }
                }
            }
            __syncthreads();
            // read transposed: thread -> (b, d); pairs along k
            const int bq = tid & 3;
            const int d  = tid >> 2;          // 0..63
            const int dg = colBase + p * 64 + d;
            uint32_t hbuf[16], lbuf[16];
            #pragma unroll
            for (int j = 0; j < 16; j++) {
                float v0 = smf[(8 * j + bq) * 68 + d];
                float v1 = smf[(8 * j + 4 + bq) * 68 + d];
                split2(make_float2(v0, v1), hbuf[j], lbuf[j]);
            }
            size_t base = ((size_t)bq * DD + dg) * LKH + (rowBase >> 3);
            #pragma unroll
            for (int i = 0; i < 4; i++) {
                *(uint4*)(oh + base + 4 * i) = make_uint4(hbuf[4*i], hbuf[4*i+1], hbuf[4*i+2], hbuf[4*i+3]);
                *(uint4*)(ol + base + 4 * i) = make_uint4(lbuf[4*i], lbuf[4*i+1], lbuf[4*i+2], lbuf[4*i+3]);
            }
        }
    }
}

#define SMEM_G128 (16 * SKS * (128 + 128))
#define SMEM_G64  (16 * SKS * (64 + 64))

// ------------------------- MMA banded attention ----------------------------
// 16 q-rows per block, grid (32, 4). K/V pre-split bf16 hi/lo in global.
#define SQS 260          // Q smem stride (u32 pairs)
#define SSW 968          // S / awsum stride (f32)
#define SMEM_ATTN ((2 * 16 * SQS + 2 * 16 * SSW + 16) * 4)

__device__ __forceinline__ int band_start(int qi) { return (qi >= 409) ? 3268 : qi * 8; }
__device__ __forceinline__ int band_wd(int qi)    { return (qi >= 409) ? 828  : 827; }

__global__ __launch_bounds__(256) void attn_mma(
        const float* __restrict__ q,
        const uint32_t* __restrict__ kh,
        const uint32_t* __restrict__ kl,
        const uint32_t* __restrict__ vth,
        const uint32_t* __restrict__ vtl,
        float* __restrict__ ctx,
        float* __restrict__ aw)
{
    extern __shared__ uint32_t sm[];
    uint32_t* sQh = sm;                         // [16][SQS]
    uint32_t* sQl = sQh + 16 * SQS;
    float*    sS  = (float*)(sQl + 16 * SQS);   // [16][SSW]
    float*    aws = sS + 16 * SSW;              // [16][SSW]
    float*    sInvH = aws + 16 * SSW;           // [16]

    const int qi0 = blockIdx.x * 16;
    const int b   = blockIdx.y;
    const int tid = threadIdx.x;
    const int lane = tid & 31;
    const int warp = tid >> 5;
    const int g = lane >> 2, t = lane & 3;

    const int ustart = band_start(qi0);
    const int uend   = band_start(qi0 + 15) + band_wd(qi0 + 15);
    const int uW     = uend - ustart;
    const int ngroups = (uW + 7) >> 3;
    const int KPAD    = ((uW + 15) >> 4) << 4;

    // stage Q (scaled by 1/8) as bf16 hi/lo pairs
    for (int i = tid; i < 16 * 256; i += 256) {
        int r = i >> 8, c = i & 255;
        float2 f = *(const float2*)(q + ((size_t)(qi0 + r) * BB + b) * DD + 2 * c);
        f.x *= 0.125f; f.y *= 0.125f;
        uint32_t h, l;
        split2(f, h, l);
        sQh[r * SQS + c] = h;
        sQl[r * SQS + c] = l;
    }

    for (int h = 0; h < HH; h++) {
        __syncthreads();

        // hoist Q a-frags for this head
        uint32_t qah[4][4], qal[4][4];
        #pragma unroll
        for (int ks = 0; ks < 4; ks++) {
            int base = g * SQS + h * 32 + ks * 8 + t;
            qah[ks][0] = sQh[base];
            qah[ks][1] = sQh[base + 8 * SQS];
            qah[ks][2] = sQh[base + 4];
            qah[ks][3] = sQh[base + 8 * SQS + 4];
            qal[ks][0] = sQl[base];
            qal[ks][1] = sQl[base + 8 * SQS];
            qal[ks][2] = sQl[base + 4];
            qal[ks][3] = sQl[base + 8 * SQS + 4];
        }

        // ---- scores: pre-split K fragments straight from global ----
        for (int grp = warp; grp < ngroups; grp += 8) {
            int key = ustart + grp * 8 + g;
            if (key > LK - 1) key = LK - 1;
            const uint32_t* krh = kh + ((size_t)key * BB + b) * (DD / 2) + h * 32;
            const uint32_t* krl = kl + ((size_t)key * BB + b) * (DD / 2) + h * 32;
            float acc[4] = {0.f, 0.f, 0.f, 0.f};
            #pragma unroll
            for (int ks = 0; ks < 4; ks++) {
                uint32_t bh[2], bl[2];
                bh[0] = krh[ks * 8 + t];
                bh[1] = krh[ks * 8 + t + 4];
                bl[0] = krl[ks * 8 + t];
                bl[1] = krl[ks * 8 + t + 4];
                mma_bf16(acc, qah[ks], bh);
                mma_bf16(acc, qah[ks], bl);
                mma_bf16(acc, qal[ks], bh);
            }
            *(float2*)(sS + g * SSW + grp * 8 + 2 * t)       = make_float2(acc[0], acc[1]);
            *(float2*)(sS + (g + 8) * SSW + grp * 8 + 2 * t) = make_float2(acc[2], acc[3]);
        }
        __syncthreads();

        // ---- softmax + head-mean accumulation + zero padding ----
        #pragma unroll
        for (int rr = 0; rr < 2; rr++) {
            const int r  = warp + rr * 8;
            const int qi = qi0 + r;
            const int j0 = band_start(qi) - ustart;
            const int W  = band_wd(qi);
            float* srow = sS + r * SSW;

            float m = -1e30f;
            for (int i = j0 + lane; i < j0 + W; i += 32) m = fmaxf(m, srow[i]);
            #pragma unroll
            for (int o = 16; o > 0; o >>= 1) m = fmaxf(m, __shfl_xor_sync(0xffffffffu, m, o));
            float sum = 0.f;
            for (int i = j0 + lane; i < j0 + W; i += 32) {
                float e = __expf(srow[i] - m);
                srow[i] = e;
                sum += e;
            }
            #pragma unroll
            for (int o = 16; o > 0; o >>= 1) sum += __shfl_xor_sync(0xffffffffu, sum, o);
            float inv = 1.0f / sum;
            if (lane == 0) sInvH[r] = inv;

            float cc = inv * 0.125f;   // 1/H
            float* arow = aws + r * SSW;
            if (h == 0) {
                for (int i = j0 + lane; i < j0 + W; i += 32) arow[i] = srow[i] * cc;
            } else {
                for (int i = j0 + lane; i < j0 + W; i += 32) arow[i] += srow[i] * cc;
            }
            for (int i = lane; i < j0; i += 32) srow[i] = 0.f;
            for (int i = j0 + W + lane; i < KPAD; i += 32) srow[i] = 0.f;
        }
        __syncthreads();

        // ---- context: pre-split V^T fragments straight from global ----
        {
            const int dimBase = h * 64 + warp * 8;
            float cacc[4] = {0.f, 0.f, 0.f, 0.f};
            const int nchunks = KPAD >> 4;
            const uint32_t* vhc = vth + ((size_t)b * DD + dimBase + g) * LKH;
            const uint32_t* vlc = vtl + ((size_t)b * DD + dimBase + g) * LKH;
            const int kbase = ustart >> 1;
            for (int ck = 0; ck < nchunks; ck++) {
                const float* pr0 = sS + g * SSW + ck * 16 + 2 * t;
                const float* pr8 = sS + (g + 8) * SSW + ck * 16 + 2 * t;
                float2 p0 = *(const float2*)(pr0);
                float2 p2 = *(const float2*)(pr8);
                float2 p1 = *(const float2*)(pr0 + 8);
                float2 p3 = *(const float2*)(pr8 + 8);
                uint32_t ah[4], al[4];
                split2(p0, ah[0], al[0]);
                split2(p2, ah[1], al[1]);
                split2(p1, ah[2], al[2]);
                split2(p3, ah[3], al[3]);

                int kp2 = kbase + ck * 8 + t;
                uint32_t bh[2], bl[2];
                bh[0] = vhc[kp2];
                bh[1] = vhc[kp2 + 4];
                bl[0] = vlc[kp2];
                bl[1] = vlc[kp2 + 4];

                mma_bf16(cacc, ah, bh);
                mma_bf16(cacc, ah, bl);
                mma_bf16(cacc, al, bh);
            }
            float inv0 = sInvH[g];
            float inv1 = sInvH[g + 8];
            *(float2*)(ctx + ((size_t)(qi0 + g) * BB + b) * DD + dimBase + 2 * t) =
                make_float2(cacc[0] * inv0, cacc[1] * inv0);
            *(float2*)(ctx + ((size_t)(qi0 + g + 8) * BB + b) * DD + dimBase + 2 * t) =
                make_float2(cacc[2] * inv1, cacc[3] * inv1);
        }
    }
    __syncthreads();

    // ---- final attn_weights write (zeros outside band) ----
    for (int i = tid; i < 16 * 1024; i += 256) {
        int r  = i >> 10;
        int c  = (i & 1023) << 2;
        int qi = qi0 + r;
        int s0 = band_start(qi);
        int W  = band_wd(qi);
        const float* arow = aws + r * SSW;
        float4 o;
        {
            int j = c + 0, jj = j - s0;
            o.x = (jj >= 0 && jj < W) ? arow[j - ustart] : 0.f;
            j = c + 1; jj = j - s0;
            o.y = (jj >= 0 && jj < W) ? arow[j - ustart] : 0.f;
            j = c + 2; jj = j - s0;
            o.z = (jj >= 0 && jj < W) ? arow[j - ustart] : 0.f;
            j = c + 3; jj = j - s0;
            o.w = (jj >= 0 && jj < W) ? arow[j - ustart] : 0.f;
        }
        *(float4*)(aw + ((size_t)b * LQ + qi) * LK + c) = o;
    }
}

// ------------------------- launch -----------------------------------------
extern "C" void kernel_launch(void* const* d_in, const int* in_sizes, int n_in,
                              void* d_out, int out_size)
{
    const float* tgt    = (const float*)d_in[0];
    const float* memory = (const float*)d_in[1];
    const float* Wq = (const float*)d_in[2];  const float* bq = (const float*)d_in[3];
    const float* Wk = (const float*)d_in[4];  const float* bk = (const float*)d_in[5];
    const float* Wv = (const float*)d_in[6];  const float* bv = (const float*)d_in[7];
    const float* Wo = (const float*)d_in[8];  const float* bo = (const float*)d_in[9];
    const float* W1 = (const float*)d_in[10]; const float* b1 = (const float*)d_in[11];
    const float* W2 = (const float*)d_in[12]; const float* b2 = (const float*)d_in[13];
    const float* ln1w = (const float*)d_in[14]; const float* ln1b = (const float*)d_in[15];
    const float* ln2w = (const float*)d_in[16]; const float* ln2b = (const float*)d_in[17];
    const float* ln3w = (const float*)d_in[18]; const float* ln3b = (const float*)d_in[19];
    const float* ln4w = (const float*)d_in[20]; const float* ln4b = (const float*)d_in[21];

    float* out    = (float*)d_out;
    float* out_x  = out;
    float* out_aw = out + (size_t)LQ * BB * DD;

    float *t_, *q_, *ctx_, *x1_, *xn_, *ff1_;
    float2* rs_;
    uint32_t *kh_, *kl_, *vth_, *vtl_;
    cudaGetSymbolAddress((void**)&t_,   g_t);
    cudaGetSymbolAddress((void**)&q_,   g_q);
    cudaGetSymbolAddress((void**)&ctx_, g_ctx);
    cudaGetSymbolAddress((void**)&x1_,  g_x1);
    cudaGetSymbolAddress((void**)&xn_,  g_xn);
    cudaGetSymbolAddress((void**)&ff1_, g_ff1);
    cudaGetSymbolAddress((void**)&rs_,  g_rs);
    cudaGetSymbolAddress((void**)&kh_,  g_kh);
    cudaGetSymbolAddress((void**)&kl_,  g_kl);
    cudaGetSymbolAddress((void**)&vth_, g_vth);
    cudaGetSymbolAddress((void**)&vtl_, g_vtl);

    cudaFuncSetAttribute(attn_mma, cudaFuncAttributeMaxDynamicSharedMemorySize, SMEM_ATTN);
    cudaFuncSetAttribute(gemm_bf16x3<128,128,0,0>, cudaFuncAttributeMaxDynamicSharedMemorySize, SMEM_G128);
    cudaFuncSetAttribute(gemm_bf16x3<128,128,1,1>, cudaFuncAttributeMaxDynamicSharedMemorySize, SMEM_G128);
    cudaFuncSetAttribute(gemm_bf16x3<128,128,2,1>, cudaFuncAttributeMaxDynamicSharedMemorySize, SMEM_G128);
    cudaFuncSetAttribute(gemm_bf16x3<64,64,0,0>,   cudaFuncAttributeMaxDynamicSharedMemorySize, SMEM_G64);

    // LN1 (materialized; needed as residual) + LN2 row stats
    ln_kernel<<<LQ * BB, 256>>>(tgt, ln1w, ln1b, t_);
    rowstat_kernel<<<(LK * BB) / 8, 256>>>(memory, rs_);

    // Q projection (float out)
    gemm_bf16x3<64,64,0,0><<<dim3(DD / 64, (LQ * BB) / 64), 256, SMEM_G64>>>(
        t_, Wq, bq, nullptr, q_, nullptr, nullptr, nullptr, nullptr, nullptr, DD, DD, 0);

    // K projection: fused LN2, packed bf16 hi/lo out
    gemm_bf16x3<128,128,1,1><<<dim3(DD / 128, (LK * BB) / 128), 256, SMEM_G128>>>(
        memory, Wk, bk, nullptr, nullptr, kh_, kl_, rs_, ln2w, ln2b, DD, DD, 0);

    // V projection: fused LN2, transposed packed bf16 hi/lo out
    gemm_bf16x3<128,128,2,1><<<dim3(DD / 128, (LK * BB) / 128), 256, SMEM_G128>>>(
        memory, Wv, bv, nullptr, nullptr, vth_, vtl_, rs_, ln2w, ln2b, DD, DD, 0);

    // MMA banded attention
    attn_mma<<<dim3(LQ / 16, BB), 256, SMEM_ATTN>>>(q_, kh_, kl_, vth_, vtl_, ctx_, out_aw);

    // output projection + residual, LN3
    gemm_bf16x3<64,64,0,0><<<dim3(DD / 64, (LQ * BB) / 64), 256, SMEM_G64>>>(
        ctx_, Wo, bo, t_, x1_, nullptr, nullptr, nullptr, nullptr, nullptr, DD, DD, 0);
    ln_kernel<<<LQ * BB, 256>>>(x1_, ln3w, ln3b, xn_);

    // FFN
    gemm_bf16x3<128,128,0,0><<<dim3(DFF / 128, (LQ * BB) / 128), 256, SMEM_G128>>>(
        xn_, W1, b1, nullptr, ff1_, nullptr, nullptr, nullptr, nullptr, nullptr, DFF, DD, 1);
    gemm_bf16x3<64,64,0,0><<<dim3(DD / 64, (LQ * BB) / 64), 256, SMEM_G64>>>(
        ff1_, W2, b2, xn_, x1_, nullptr, nullptr, nullptr, nullptr, nullptr, DD, DFF, 0);

    // LN4 -> output x
    ln_kernel<<<LQ * BB, 256>>>(x1_, ln4w, ln4b, out_x);
}